// round 12
// baseline (speedup 1.0000x reference)
#include <cuda_runtime.h>
#include <cuda_fp16.h>
#include <math.h>
#include <stdint.h>

// ---------------------------------------------------------------------------
// EfficientFrequencyAttention  B=8, C=256, H=W=64
// Round 12: round-11 + ldmatrix (LDSM) fragment loads in gemm_h / gram_h.
// ---------------------------------------------------------------------------
#define Bn  8
#define Cn  256
#define HWn 4096
#define BCHW (Bn*Cn*HWn)   // 8,388,608
#define BCC  (Bn*Cn*Cn)    // 524,288
#define SPLITK 8

// ----------------------------- scratch (static, no allocation) -------------
__device__ __half g_Xt  [BCHW];          // x transposed fp16: [b][n][c]
__device__ __half g_Qt  [BCHW];          // softmax_c(Q) transposed fp16: [b][n][c]
__device__ __half g_Wh  [4 * Cn * Cn];   // fp16 Wk,Wq,Wv,Wr  [m][k]
__device__ __half g_Ctxh[BCC];           // ctx fp16
__device__ __half g_Mch [BCC];           // combined final A fp16 [m][k]
__device__ float  g_K   [BCHW];          // conv K fp32 [c][n]
__device__ float  g_Q   [BCHW];          // conv Q fp32 [c][n]
__device__ float  g_V   [BCHW];          // conv V fp32 [c][n]
__device__ float  g_G1  [BCHW];
__device__ float  g_G2  [BCHW];
__device__ float  g_Attm[BCC];
__device__ float  g_Meff[BCC];
__device__ float  g_Part[BCC * SPLITK];  // ONE reused split-K slab (L2-resident)
__device__ float  g_Bias[Cn];
__device__ float2 g_Stat[4 * Bn * Cn];   // [K, L0, L1, L2]

// ----------------------------- helpers -------------------------------------
__device__ __forceinline__ void mma16(float* c, const unsigned* a, const unsigned* b) {
    asm volatile(
        "mma.sync.aligned.m16n8k16.row.col.f32.f16.f16.f32 "
        "{%0,%1,%2,%3},{%4,%5,%6,%7},{%8,%9},{%0,%1,%2,%3};\n"
        : "+f"(c[0]), "+f"(c[1]), "+f"(c[2]), "+f"(c[3])
        : "r"(a[0]), "r"(a[1]), "r"(a[2]), "r"(a[3]),
          "r"(b[0]), "r"(b[1]));
}

__device__ __forceinline__ void ldsm4(unsigned& r0, unsigned& r1,
                                      unsigned& r2, unsigned& r3, uint32_t addr) {
    asm volatile("ldmatrix.sync.aligned.m8n8.x4.shared.b16 {%0,%1,%2,%3}, [%4];"
        : "=r"(r0), "=r"(r1), "=r"(r2), "=r"(r3) : "r"(addr));
}

__device__ __forceinline__ void cp16(uint32_t dst, const void* src) {
    asm volatile("cp.async.ca.shared.global [%0], [%1], 16;" :: "r"(dst), "l"(src));
}
#define CP_COMMIT() asm volatile("cp.async.commit_group;")
#define CP_WAIT1()  asm volatile("cp.async.wait_group 1;")
#define CP_WAIT0()  asm volatile("cp.async.wait_group 0;")

// fp16 tile: 128 rows x 32 k-halves, row stride 20 half2 (80 B)
#define HS2   20
#define TILE_U (128 * HS2)       // 2560 half2
#define TILE_B (TILE_U * 4)      // 10240 bytes

// ---------------------------------------------------------------------------
// ldmatrix-based chunk: per warp-chunk 12 LDSM.x4 + 32 HMMA (was 48 LDS.32).
// aTile/bTile: smem BYTE addresses of the stage tiles.
// aOff[2]/bOff[4]: per-lane invariant byte offsets (see setup in kernels).
//   A x4 (per mi, ks): quads -> (rows +0-7 / +8-15) x (k 0-7 / 8-15 halves),
//     reg order a0,a1,a2,a3 of the m16n8k16 fragment.
//   B x4 (per pair p, ks): quads -> (tile 2p rows, k lo/hi; tile 2p+1 rows,
//     k lo/hi), reg order b0(2p), b1(2p), b0(2p+1), b1(2p+1).
// Bank check: 8 rows @80B start at banks {0,20,8,28,16,4,24,12}+c, 4 words
// each -> all 32 banks, conflict-free per phase.
// ---------------------------------------------------------------------------
__device__ __forceinline__ void gemm_chunk_ldsm(uint32_t aTile, uint32_t bTile,
                                                const uint32_t aOff[2],
                                                const uint32_t bOff[4],
                                                float acc[2][8][4])
{
    #pragma unroll
    for (int ks = 0; ks < 2; ks++) {
        const uint32_t ka = ks * 32;     // 8 half2 = 32 bytes per k16 step
        unsigned af[2][4], bf[8][2];
        #pragma unroll
        for (int mi = 0; mi < 2; mi++)
            ldsm4(af[mi][0], af[mi][1], af[mi][2], af[mi][3],
                  aTile + aOff[mi] + ka);
        #pragma unroll
        for (int p = 0; p < 4; p++)
            ldsm4(bf[2 * p][0], bf[2 * p][1], bf[2 * p + 1][0], bf[2 * p + 1][1],
                  bTile + bOff[p] + ka);
        #pragma unroll
        for (int mi = 0; mi < 2; mi++)
            #pragma unroll
            for (int ni = 0; ni < 8; ni++)
                mma16(acc[mi][ni], af[mi], bf[ni]);
    }
}

// ---------------------------------------------------------------------------
// gemm_h (fp16 NT): Y[b,m,n] = sum_k A[(b),m,k] * B[b,n,k] (+ bias[m])
// ---------------------------------------------------------------------------
__global__ __launch_bounds__(256)
void gemm_h(const __half* __restrict__ A, size_t aStride,
            const __half* __restrict__ B, size_t bStride,
            const float* __restrict__ bias,
            float* __restrict__ Y, int ldY, size_t yStride)
{
    extern __shared__ unsigned sm[];
    uint32_t sb = (uint32_t)__cvta_generic_to_shared(sm);

    const int b  = blockIdx.z;
    const int m0 = blockIdx.y * 128;
    const int n0 = blockIdx.x * 128;
    const int t  = threadIdx.x;
    const __half* Ab = A + (size_t)b * aStride;
    const __half* Bb = B + (size_t)b * bStride;

    const int lane = t & 31, warp = t >> 5;
    const int wm = (warp & 3) * 32, wn = (warp >> 2) * 64;
    const int quad = lane >> 3, r8 = lane & 7;

    uint32_t aOff[2], bOff[4];
    #pragma unroll
    for (int mi = 0; mi < 2; mi++)
        aOff[mi] = (uint32_t)((wm + mi * 16 + 8 * (quad & 1) + r8) * 80 + (quad >> 1) * 16);
    #pragma unroll
    for (int p = 0; p < 4; p++)
        bOff[p] = (uint32_t)((wn + 16 * p + 8 * (quad >> 1) + r8) * 80 + (quad & 1) * 16);

    float acc[2][8][4] = {};

    auto issue = [&](int c, int st) {
        const int kc = c * 32;
        #pragma unroll
        for (int i = 0; i < 2; i++) {
            int s = t + i * 256;
            int row = s >> 2, f4 = s & 3;
            cp16(sb + (uint32_t)(st * TILE_U + row * HS2 + f4 * 4) * 4,
                 Ab + (size_t)(m0 + row) * Cn + kc + f4 * 8);
        }
        #pragma unroll
        for (int i = 0; i < 2; i++) {
            int s = t + i * 256;
            int row = s >> 2, f4 = s & 3;
            cp16(sb + (uint32_t)(2 * TILE_U + st * TILE_U + row * HS2 + f4 * 4) * 4,
                 Bb + (size_t)(n0 + row) * Cn + kc + f4 * 8);
        }
        CP_COMMIT();
    };

    issue(0, 0);
    const int NC = Cn / 32;
    for (int c = 0; c < NC; c++) {
        int st = c & 1;
        if (c + 1 < NC) { issue(c + 1, st ^ 1); CP_WAIT1(); }
        else            { CP_WAIT0(); }
        __syncthreads();
        gemm_chunk_ldsm(sb + st * TILE_B, sb + 2 * TILE_B + st * TILE_B,
                        aOff, bOff, acc);
        __syncthreads();
    }

    const int g = lane >> 2, t4 = lane & 3;
    float* Yb = Y + (size_t)b * yStride;
    #pragma unroll
    for (int mi = 0; mi < 2; mi++) {
        int r0 = m0 + wm + mi * 16 + g, r1 = r0 + 8;
        float bv0 = bias ? bias[r0] : 0.f;
        float bv1 = bias ? bias[r1] : 0.f;
        #pragma unroll
        for (int ni = 0; ni < 8; ni++) {
            int col = n0 + wn + ni * 8 + 2 * t4;
            float2 v0 = {acc[mi][ni][0] + bv0, acc[mi][ni][1] + bv0};
            float2 v1 = {acc[mi][ni][2] + bv1, acc[mi][ni][3] + bv1};
            *(float2*)&Yb[(size_t)r0 * ldY + col] = v0;
            *(float2*)&Yb[(size_t)r1 * ldY + col] = v1;
        }
    }
}

// ---------------------------------------------------------------------------
// gram_h (fp16 NT, split-K, on-the-fly softmax), ldmatrix inner loop.
// part[z,m,n] = sum_{k in split} softmax(A1-A2)[m,k] * (B1-B2)[n,k]
// grid (2, 2, Bn*SPLITK)
// ---------------------------------------------------------------------------
__global__ __launch_bounds__(256)
void gram_h(const float* __restrict__ A1, const float* __restrict__ A2,
            const float2* __restrict__ st,
            const float* __restrict__ B1, const float* __restrict__ B2,
            float* __restrict__ part)
{
    extern __shared__ unsigned sm[];
    unsigned* As = sm;
    unsigned* Bs = sm + 2 * TILE_U;
    uint32_t sb = (uint32_t)__cvta_generic_to_shared(sm);

    const int z = blockIdx.z, b = z >> 3, s = z & 7;
    const int m0 = blockIdx.y * 128;
    const int n0 = blockIdx.x * 128;
    const int kb = s * (HWn / SPLITK);
    const int t = threadIdx.x;
    const size_t bo = (size_t)b * Cn * HWn;

    const int lane = t & 31, warp = t >> 5;
    const int wm = (warp & 3) * 32, wn = (warp >> 2) * 64;
    const int quad = lane >> 3, r8 = lane & 7;
    const int lr = t >> 3, lc = (t & 7) * 4;

    uint32_t aOff[2], bOff[4];
    #pragma unroll
    for (int mi = 0; mi < 2; mi++)
        aOff[mi] = (uint32_t)((wm + mi * 16 + 8 * (quad & 1) + r8) * 80 + (quad >> 1) * 16);
    #pragma unroll
    for (int p = 0; p < 4; p++)
        bOff[p] = (uint32_t)((wn + 16 * p + 8 * (quad >> 1) + r8) * 80 + (quad & 1) * 16);

    const float2* stb = st + b * Cn;

    float acc[2][8][4] = {};
    float4 pa[4], pb[4];
    float2 ps[4];
    #pragma unroll
    for (int i = 0; i < 4; i++) ps[i] = stb[m0 + lr + i * 32];

    auto ldg = [&](int c) {
        const int kc = kb + c * 32;
        #pragma unroll
        for (int i = 0; i < 4; i++) {
            int row = lr + i * 32;
            size_t ia = bo + (size_t)(m0 + row) * HWn + kc + lc;
            pa[i] = *(const float4*)(A1 + ia);
            if (A2) {
                float4 q = *(const float4*)(A2 + ia);
                pa[i].x -= q.x; pa[i].y -= q.y; pa[i].z -= q.z; pa[i].w -= q.w;
            }
            size_t ib = bo + (size_t)(n0 + row) * HWn + kc + lc;
            pb[i] = *(const float4*)(B1 + ib);
            if (B2) {
                float4 q = *(const float4*)(B2 + ib);
                pb[i].x -= q.x; pb[i].y -= q.y; pb[i].z -= q.z; pb[i].w -= q.w;
            }
        }
    };
    auto sts = [&](int stg) {
        unsigned* Ab = As + stg * TILE_U;
        unsigned* Bb = Bs + stg * TILE_U;
        #pragma unroll
        for (int i = 0; i < 4; i++) {
            int row = lr + i * 32;
            float mx = ps[i].x, inv = ps[i].y;
            __half2 a0 = __floats2half2_rn(expf(pa[i].x - mx) * inv,
                                           expf(pa[i].y - mx) * inv);
            __half2 a1 = __floats2half2_rn(expf(pa[i].z - mx) * inv,
                                           expf(pa[i].w - mx) * inv);
            __half2 b0 = __floats2half2_rn(pb[i].x, pb[i].y);
            __half2 b1 = __floats2half2_rn(pb[i].z, pb[i].w);
            Ab[row * HS2 + (lc >> 1)]     = *(unsigned*)&a0;
            Ab[row * HS2 + (lc >> 1) + 1] = *(unsigned*)&a1;
            Bb[row * HS2 + (lc >> 1)]     = *(unsigned*)&b0;
            Bb[row * HS2 + (lc >> 1) + 1] = *(unsigned*)&b1;
        }
    };

    ldg(0);
    const int NC = (HWn / SPLITK) / 32;  // 16
    for (int c = 0; c < NC; c++) {
        int stg = c & 1;
        sts(stg);
        if (c + 1 < NC) ldg(c + 1);
        __syncthreads();
        gemm_chunk_ldsm(sb + stg * TILE_B, sb + 2 * TILE_B + stg * TILE_B,
                        aOff, bOff, acc);
        // single sync per iter: buffer stg next overwritten at iter c+2,
        // after sync(c+1) which follows every warp's mma of iter c.
    }

    const int g = lane >> 2, t4 = lane & 3;
    float* P = part + (size_t)z * Cn * Cn;
    #pragma unroll
    for (int mi = 0; mi < 2; mi++) {
        int r0 = m0 + wm + mi * 16 + g, r1 = r0 + 8;
        #pragma unroll
        for (int ni = 0; ni < 8; ni++) {
            int col = n0 + wn + ni * 8 + 2 * t4;
            *(float2*)&P[(size_t)r0 * Cn + col] = make_float2(acc[mi][ni][0], acc[mi][ni][1]);
            *(float2*)&P[(size_t)r1 * Cn + col] = make_float2(acc[mi][ni][2], acc[mi][ni][3]);
        }
    }
}

// ---------------------------------------------------------------------------
// prep_x: x fp32 [b][c][n] -> Xt fp16 [b][n][c].  grid (HW/64, C/64, B)
// ---------------------------------------------------------------------------
__global__ __launch_bounds__(256)
void prep_x(const float* __restrict__ x, __half* __restrict__ Xt)
{
    __shared__ float smt[64][65];
    const int b = blockIdx.z;
    const int c0 = blockIdx.y * 64;
    const int n0 = blockIdx.x * 64;
    const int t = threadIdx.x;
    const float* xb = x + (size_t)b * Cn * HWn;

    #pragma unroll
    for (int i = 0; i < 16; i++) {
        int idx = t + i * 256;
        int c = idx >> 6, nn = idx & 63;
        smt[c][nn] = xb[(size_t)(c0 + c) * HWn + n0 + nn];
    }
    __syncthreads();
    __half* ob = Xt + (size_t)b * HWn * Cn;
    #pragma unroll
    for (int i = 0; i < 2; i++) {
        int s = t + i * 256;
        int n = s >> 3, c8 = (s & 7) * 8;
        __half2 h[4];
        #pragma unroll
        for (int j = 0; j < 4; j++)
            h[j] = __floats2half2_rn(smt[c8 + 2 * j][n], smt[c8 + 2 * j + 1][n]);
        *(float4*)&ob[(size_t)(n0 + n) * Cn + c0 + c8] = *(float4*)h;
    }
}

// ---------------------------------------------------------------------------
// round4_h: fp16-round all 4 weight matrices + w0*br bias. 256 blocks.
// ---------------------------------------------------------------------------
__global__ __launch_bounds__(256)
void round4_h(const float* __restrict__ Wk, const float* __restrict__ Wq,
              const float* __restrict__ Wv, const float* __restrict__ Wr,
              const float* __restrict__ br, const float* __restrict__ wdw,
              __half* __restrict__ dst, float* __restrict__ bias)
{
    int i = blockIdx.x * 256 + threadIdx.x;
    dst[i]               = __float2half_rn(Wk[i]);
    dst[i + 1 * Cn * Cn] = __float2half_rn(Wq[i]);
    dst[i + 2 * Cn * Cn] = __float2half_rn(Wv[i]);
    dst[i + 3 * Cn * Cn] = __float2half_rn(Wr[i]);
    if (blockIdx.x == 0) bias[threadIdx.x] = wdw[2 * threadIdx.x] * br[threadIdx.x];
}

// ---------------------------------------------------------------------------
// row stats for K
// ---------------------------------------------------------------------------
__global__ __launch_bounds__(256)
void row_stats(const float* __restrict__ A, float2* __restrict__ st)
{
    __shared__ float red[256];
    const size_t base = (size_t)blockIdx.x * HWn;
    const int t = threadIdx.x;

    float v[16];
    float m = -INFINITY;
    #pragma unroll
    for (int i = 0; i < 16; i++) {
        v[i] = A[base + t + i * 256];
        m = fmaxf(m, v[i]);
    }
    red[t] = m; __syncthreads();
    for (int s = 128; s > 0; s >>= 1) {
        if (t < s) red[t] = fmaxf(red[t], red[t + s]);
        __syncthreads();
    }
    m = red[0]; __syncthreads();

    float sum = 0.f;
    #pragma unroll
    for (int i = 0; i < 16; i++) sum += expf(v[i] - m);
    red[t] = sum; __syncthreads();
    for (int s = 128; s > 0; s >>= 1) {
        if (t < s) red[t] += red[t + s];
        __syncthreads();
    }
    if (t == 0) st[blockIdx.x] = make_float2(m, 1.0f / red[0]);
}

// ---------------------------------------------------------------------------
// shuffle block reductions (256 threads); second stage reduces the 8 warp
// partials exactly once per 8-lane xor group (no scaling).
// ---------------------------------------------------------------------------
__device__ __forceinline__ float blk_max(float v, float* red, int t)
{
    #pragma unroll
    for (int o = 16; o > 0; o >>= 1)
        v = fmaxf(v, __shfl_xor_sync(0xffffffffu, v, o));
    if ((t & 31) == 0) red[t >> 5] = v;
    __syncthreads();
    if (t < 32) {
        float r = red[t & 7];
        #pragma unroll
        for (int o = 4; o > 0; o >>= 1)
            r = fmaxf(r, __shfl_xor_sync(0xffffffffu, r, o));
        if (t == 0) red[0] = r;
    }
    __syncthreads();
    float out = red[0];
    __syncthreads();
    return out;
}

__device__ __forceinline__ float blk_sum(float v, float* red, int t)
{
    #pragma unroll
    for (int o = 16; o > 0; o >>= 1)
        v += __shfl_xor_sync(0xffffffffu, v, o);
    if ((t & 31) == 0) red[t >> 5] = v;
    __syncthreads();
    if (t < 32) {
        float r = red[t & 7];
        #pragma unroll
        for (int o = 4; o > 0; o >>= 1)
            r += __shfl_xor_sync(0xffffffffu, r, o);
        if (t == 0) red[0] = r;
    }
    __syncthreads();
    float out = red[0];
    __syncthreads();
    return out;
}

// ---------------------------------------------------------------------------
// gauss_pyr: full Laplacian pyramid in ONE kernel. One block per (b,c) image.
// ---------------------------------------------------------------------------
struct G5 { float w[5]; };

__global__ __launch_bounds__(256)
void gauss_pyr(const float* __restrict__ x, float* __restrict__ G1o,
               float* __restrict__ G2o, G5 w3, G5 w5,
               float2* __restrict__ stL0, float2* __restrict__ stL1,
               float2* __restrict__ stL2)
{
    __shared__ float sa[68][72];
    __shared__ float sb_[68][72];
    __shared__ float red[8];

    const int img = blockIdx.x;
    const int t = threadIdx.x;
    const float* ip = x + (size_t)img * HWn;

    for (int i = t; i < 68 * 72; i += 256) {
        (&sa[0][0])[i] = 0.f;
        (&sb_[0][0])[i] = 0.f;
    }
    __syncthreads();

    float xv[16];
    #pragma unroll
    for (int i = 0; i < 16; i++) {
        int px = t + i * 256;
        xv[i] = ip[px];
        sa[(px >> 6) + 2][(px & 63) + 2] = xv[i];
    }
    __syncthreads();

    {
        float m = -INFINITY;
        #pragma unroll
        for (int i = 0; i < 16; i++) m = fmaxf(m, xv[i]);
        m = blk_max(m, red, t);
        float s = 0.f;
        #pragma unroll
        for (int i = 0; i < 16; i++) s += expf(xv[i] - m);
        s = blk_sum(s, red, t);
        if (t == 0) stL0[img] = make_float2(m, 1.0f / s);
    }

    #pragma unroll
    for (int i = 0; i < 16; i++) {
        int px = t + i * 256, y = (px >> 6) + 2, c = (px & 63) + 2;
        float a = 0.f;
        #pragma unroll
        for (int d = 0; d < 5; d++) a += w3.w[d] * sa[y][c + d - 2];
        sb_[y][c] = a;
    }
    __syncthreads();

    float g1[16];
    float* op1 = G1o + (size_t)img * HWn;
    #pragma unroll
    for (int i = 0; i < 16; i++) {
        int px = t + i * 256, y = (px >> 6) + 2, c = (px & 63) + 2;
        float a = 0.f;
        #pragma unroll
        for (int d = 0; d < 5; d++) a += w3.w[d] * sb_[y + d - 2][c];
        g1[i] = a;
        op1[px] = a;
    }

    {
        float m = -INFINITY;
        #pragma unroll
        for (int i = 0; i < 16; i++) m = fmaxf(m, xv[i] - g1[i]);
        m = blk_max(m, red, t);
        float s = 0.f;
        #pragma unroll
        for (int i = 0; i < 16; i++) s += expf(xv[i] - g1[i] - m);
        s = blk_sum(s, red, t);
        if (t == 0) stL1[img] = make_float2(m, 1.0f / s);
    }

    #pragma unroll
    for (int i = 0; i < 16; i++) {
        int px = t + i * 256;
        sa[(px >> 6) + 2][(px & 63) + 2] = g1[i];
    }
    __syncthreads();

    #pragma unroll
    for (int i = 0; i < 16; i++) {
        int px = t + i * 256, y = (px >> 6) + 2, c = (px & 63) + 2;
        float a = 0.f;
        #pragma unroll
        for (int d = 0; d < 5; d++) a += w5.w[d] * sa[y][c + d - 2];
        sb_[y][c] = a;
    }
    __syncthreads();

    float dv[16];
    float* op2 = G2o + (size_t)img * HWn;
    #pragma unroll
    for (int i = 0; i < 16; i++) {
        int px = t + i * 256, y = (px >> 6) + 2, c = (px & 63) + 2;
        float a = 0.f;
        #pragma unroll
        for (int d = 0; d < 5; d++) a += w5.w[d] * sb_[y + d - 2][c];
        op2[px] = a;
        dv[i] = g1[i] - a;
    }
    {
        float m = -INFINITY;
        #pragma unroll
        for (int i = 0; i < 16; i++) m = fmaxf(m, dv[i]);
        m = blk_max(m, red, t);
        float s = 0.f;
        #pragma unroll
        for (int i = 0; i < 16; i++) s += expf(dv[i] - m);
        s = blk_sum(s, red, t);
        if (t == 0) stL2[img] = make_float2(m, 1.0f / s);
    }
}

// ---------------------------------------------------------------------------
// softmax over channel axis (256) of Q fp32 [c][n]; writes Qt fp16 [n][c].
// ---------------------------------------------------------------------------
__global__ __launch_bounds__(256)
void softmax_c_qt(const float* __restrict__ Q, __half* __restrict__ Qt)
{
    extern __shared__ float smf[];
    const int P = 65;
    float* red = smf + 256 * P;
    const int blk = blockIdx.x;
    const int b = blk >> 6, n0 = (blk & 63) * 64;
    const float* base = Q + (size_t)b * Cn * HWn + n0;
    const int t = threadIdx.x, nl = t & 63, cs = t >> 6;

    #pragma unroll 4
    for (int i = 0; i < 64; i++) {
        int c = cs * 64 + i;
        smf[c * P + nl] = base[(size_t)c * HWn + nl];
    }
    __syncthreads();
    float m = -INFINITY;
    #pragma unroll 4
    for (int i = 0; i < 64; i++) m = fmaxf(m, smf[(cs * 64 + i) * P + nl]);
    red[cs * 64 + nl] = m;
    __syncthreads();
    if (t < 64)
        red[t] = fmaxf(fmaxf(red[t], red[64 + t]), fmaxf(red[128 + t], red[192 + t]));
    __syncthreads();
    m = red[nl];
    __syncthreads();
    float s = 0.f;
    #pragma unroll 4
    for (int i = 0; i < 64; i++) {
        int c = cs * 64 + i;
        float e = expf(smf[c * P + nl] - m);
        smf[c * P + nl] = e;
        s += e;
    }
    red[cs * 64 + nl] = s;
    __syncthreads();
    if (t < 64) red[t] = red[t] + red[64 + t] + red[128 + t] + red[192 + t];
    __syncthreads();
    float inv = 1.0f / red[nl];
    __half* ob = Qt + (size_t)b * HWn * Cn + (size_t)(n0 + nl) * Cn;
    #pragma unroll
    for (int i = 0; i < 64; i += 8) {
        int c = cs * 64 + i;
        __half2 h[4];
        #pragma unroll
        for (int j = 0; j < 4; j++)
            h[j] = __floats2half2_rn(smf[(c + 2 * j) * P + nl] * inv,
                                     smf[(c + 2 * j + 1) * P + nl] * inv);
        *(float4*)&ob[c] = *(float4*)h;
    }
}

// ---------------------------------------------------------------------------
// ctx reduce -> fp16
// ---------------------------------------------------------------------------
__global__ __launch_bounds__(256)
void reduce_ctx_h(const float* __restrict__ part, __half* __restrict__ ctx)
{
    const int e = blockIdx.x * 256 + threadIdx.x;
    const int b = e >> 16, r = e & 65535;
    float v = 0.f;
    #pragma unroll
    for (int s = 0; s < SPLITK; s++)
        v += part[((size_t)(b * SPLITK + s) << 16) + r];
    ctx[e] = __float2half_rn(v);
}

// ---------------------------------------------------------------------------
// row softmax (256) of split-K gram partials, accumulate into att (fp32)
// ---------------------------------------------------------------------------
__global__ __launch_bounds__(256)
void softmax_rows_accum(const float* __restrict__ part, float* __restrict__ att, int init)
{
    __shared__ float red[256];
    const int row = blockIdx.x;
    const int b = row >> 8, i = row & 255;
    const int t = threadIdx.x;

    float v = 0.f;
    size_t base = ((size_t)b * SPLITK << 16) + (size_t)i * Cn + t;
    #pragma unroll
    for (int s = 0; s < SPLITK; s++) v += part[base + ((size_t)s << 16)];

    red[t] = v; __syncthreads();
    for (int s = 128; s > 0; s >>= 1) {
        if (t < s) red[t] = fmaxf(red[t], red[t + s]);
        __syncthreads();
    }
    float m = red[0]; __syncthreads();
    float e = expf(v - m);
    red[t] = e; __syncthreads();
    for (int s = 128; s > 0; s >>= 1) {
        if (t < s) red[t] += red[t + s];
        __syncthreads();
    }
    float r = e / red[0];
    size_t o = (size_t)row * Cn + t;
    att[o] = init ? r : (att[o] + r);
}

// ---------------------------------------------------------------------------
// Mc[b][m][k] = fp16( w0[m]*Meff[b][m][k] + w1[m]*att[b][k][m] )
// ---------------------------------------------------------------------------
__global__ __launch_bounds__(256)
void combine_mc_h(const float* __restrict__ Meff, const float* __restrict__ att,
                  const float* __restrict__ wdw, __half* __restrict__ Mc)
{
    __shared__ float ts[32][33];
    const int b = blockIdx.z, m0 = blockIdx.y * 32, k0 = blockIdx.x * 32;
    const int tx = threadIdx.x & 31, ty = threadIdx.x >> 5;
    const float* attb = att + (size_t)b * Cn * Cn;

    #pragma unroll
    for (int j = 0; j < 4; j++)
        ts[ty + j * 8][tx] = attb[(size_t)(k0 + ty + j * 8) * Cn + m0 + tx];
    __syncthreads();

    const float* mb = Meff + (size_t)b * Cn * Cn;
    __half* ob = Mc + (size_t)b * Cn * Cn;
    #pragma unroll
    for (int j = 0; j < 4; j++) {
        int m = m0 + ty + j * 8, k = k0 + tx;
        float w0 = wdw[2 * m], w1 = wdw[2 * m + 1];
        ob[(size_t)m * Cn + k] =
            __float2half_rn(w0 * mb[(size_t)m * Cn + k] + w1 * ts[tx][ty + j * 8]);
    }
}

// ---------------------------------------------------------------------------
// host
// ---------------------------------------------------------------------------
static void make_gauss1d(int ksize, double sigma, float* w)
{
    double g[5], s = 0.0;
    for (int i = 0; i < ksize; i++) {
        double d = (double)i - (ksize - 1) / 2.0;
        g[i] = exp(-(d * d) / (2.0 * sigma * sigma));
        s += g[i];
    }
    for (int i = 0; i < ksize; i++) w[i] = (float)(g[i] / s);
}

extern "C" void kernel_launch(void* const* d_in, const int* in_sizes, int n_in,
                              void* d_out, int out_size)
{
    (void)in_sizes; (void)n_in; (void)out_size;
    const float* x   = (const float*)d_in[0];
    const float* Wk  = (const float*)d_in[1];
    const float* bk  = (const float*)d_in[2];
    const float* Wq  = (const float*)d_in[3];
    const float* bq  = (const float*)d_in[4];
    const float* Wv  = (const float*)d_in[5];
    const float* bv  = (const float*)d_in[6];
    const float* Wr  = (const float*)d_in[7];
    const float* br  = (const float*)d_in[8];
    const float* wdw = (const float*)d_in[9];
    float* out = (float*)d_out;

    __half *gXt, *gQt, *gWh, *gCtxh, *gMch;
    float *gK, *gQ, *gV, *gG1, *gG2, *gAttm, *gMeff, *gPart, *gBias;
    float2* gSt;
    cudaGetSymbolAddress((void**)&gXt,   g_Xt);
    cudaGetSymbolAddress((void**)&gQt,   g_Qt);
    cudaGetSymbolAddress((void**)&gWh,   g_Wh);
    cudaGetSymbolAddress((void**)&gCtxh, g_Ctxh);
    cudaGetSymbolAddress((void**)&gMch,  g_Mch);
    cudaGetSymbolAddress((void**)&gK,    g_K);
    cudaGetSymbolAddress((void**)&gQ,    g_Q);
    cudaGetSymbolAddress((void**)&gV,    g_V);
    cudaGetSymbolAddress((void**)&gG1,   g_G1);
    cudaGetSymbolAddress((void**)&gG2,   g_G2);
    cudaGetSymbolAddress((void**)&gAttm, g_Attm);
    cudaGetSymbolAddress((void**)&gMeff, g_Meff);
    cudaGetSymbolAddress((void**)&gPart, g_Part);
    cudaGetSymbolAddress((void**)&gBias, g_Bias);
    cudaGetSymbolAddress((void**)&gSt,   g_Stat);

    float2* stK  = gSt + 0 * Bn * Cn;
    float2* stL0 = gSt + 1 * Bn * Cn;
    float2* stL1 = gSt + 2 * Bn * Cn;
    float2* stL2 = gSt + 3 * Bn * Cn;

    const int SM_GEMM = 4 * TILE_B;              // 40960
    const int SM_SMC  = (256 * 65 + 512) * 4;    // 68608
    cudaFuncSetAttribute(gemm_h,        cudaFuncAttributeMaxDynamicSharedMemorySize, SM_GEMM);
    cudaFuncSetAttribute(gram_h,        cudaFuncAttributeMaxDynamicSharedMemorySize, SM_GEMM);
    cudaFuncSetAttribute(softmax_c_qt,  cudaFuncAttributeMaxDynamicSharedMemorySize, SM_SMC);

    const double SIGMA = 1.6;
    const double S_VAL = cbrt(2.0);
    G5 g3 = {}, g5 = {};
    float t3[5];
    make_gauss1d(3, SIGMA, t3);
    g3.w[0] = 0.f; g3.w[1] = t3[0]; g3.w[2] = t3[1]; g3.w[3] = t3[2]; g3.w[4] = 0.f;
    make_gauss1d(5, SIGMA * S_VAL, g5.w);

    dim3 gConv(HWn / 128, Cn / 128, Bn);          // (32, 2, 8)
    dim3 gGram(Cn / 128, Cn / 128, Bn * SPLITK);  // (2, 2, 64)
    dim3 gMeffG(Cn / 128, Cn / 128, Bn);          // (2, 2, 8)
    dim3 gComb(Cn / 32, Cn / 32, Bn);             // (8, 8, 8)
    dim3 gPrep(HWn / 64, Cn / 64, Bn);            // (64, 4, 8)

    // prep: weights fp16 + bias fold; x transpose fp16
    round4_h<<<Cn * Cn / 256, 256>>>(Wk, Wq, Wv, Wr, br, wdw, gWh, gBias);
    prep_x<<<gPrep, 256>>>(x, gXt);

    // 1x1 convs: Y = W @ Xt^T
    gemm_h<<<gConv, 256, SM_GEMM>>>(gWh + 0 * Cn * Cn, 0, gXt, (size_t)HWn * Cn,
                                    bk, gK, HWn, (size_t)Cn * HWn);
    gemm_h<<<gConv, 256, SM_GEMM>>>(gWh + 1 * Cn * Cn, 0, gXt, (size_t)HWn * Cn,
                                    bq, gQ, HWn, (size_t)Cn * HWn);
    gemm_h<<<gConv, 256, SM_GEMM>>>(gWh + 2 * Cn * Cn, 0, gXt, (size_t)HWn * Cn,
                                    bv, gV, HWn, (size_t)Cn * HWn);

    // stats + channel softmax (Q -> Qt fp16)
    row_stats<<<Bn * Cn, 256>>>(gK, stK);
    softmax_c_qt<<<Bn * 64, 256, SM_SMC>>>(gQ, gQt);

    // fused Gaussian pyramid + all Laplacian stats (ONE launch)
    gauss_pyr<<<Bn * Cn, 256>>>(x, gG1, gG2, g3, g5, stL0, stL1, stL2);

    // efficient attention: ctx = softmax(K) @ V^T
    gram_h<<<gGram, 256, SM_GEMM>>>(gK, nullptr, stK, gV, nullptr, gPart);
    reduce_ctx_h<<<BCC / 256, 256>>>(gPart, gCtxh);

    // Meff = Wr @ ctx^T
    gemm_h<<<gMeffG, 256, SM_GEMM>>>(gWh + 3 * (size_t)Cn * Cn, 0,
                                     gCtxh, (size_t)Cn * Cn,
                                     nullptr, gMeff, Cn, (size_t)Cn * Cn);

    // channel attention: 3 Laplacian levels (single reused part buffer)
    gram_h<<<gGram, 256, SM_GEMM>>>(x, nullptr, stL0, x, nullptr, gPart);
    softmax_rows_accum<<<Bn * Cn, 256>>>(gPart, gAttm, 1);

    gram_h<<<gGram, 256, SM_GEMM>>>(x, gG1, stL1, x, gG1, gPart);
    softmax_rows_accum<<<Bn * Cn, 256>>>(gPart, gAttm, 0);

    gram_h<<<gGram, 256, SM_GEMM>>>(gG1, gG2, stL2, gG1, gG2, gPart);
    softmax_rows_accum<<<Bn * Cn, 256>>>(gPart, gAttm, 0);

    // fold: out = Mc @ Qt^T + w0*br
    combine_mc_h<<<gComb, 256>>>(gMeff, gAttm, wdw, gMch);
    gemm_h<<<gConv, 256, SM_GEMM>>>(gMch, (size_t)Cn * Cn,
                                    gQt, (size_t)HWn * Cn,
                                    gBias, out, HWn, (size_t)Cn * HWn);
}

// round 13
// speedup vs baseline: 1.2178x; 1.2178x over previous
#include <cuda_runtime.h>
#include <cuda_fp16.h>
#include <math.h>
#include <stdint.h>

// ---------------------------------------------------------------------------
// EfficientFrequencyAttention  B=8, C=256, H=W=64
// Round 13: LDSM inner loop ONLY in gemm_h (cheap producer);
//           gram_h reverted to round-11 scalar-LDS loop (94-reg producer).
// ---------------------------------------------------------------------------
#define Bn  8
#define Cn  256
#define HWn 4096
#define BCHW (Bn*Cn*HWn)   // 8,388,608
#define BCC  (Bn*Cn*Cn)    // 524,288
#define SPLITK 8

// ----------------------------- scratch (static, no allocation) -------------
__device__ __half g_Xt  [BCHW];          // x transposed fp16: [b][n][c]
__device__ __half g_Qt  [BCHW];          // softmax_c(Q) transposed fp16: [b][n][c]
__device__ __half g_Wh  [4 * Cn * Cn];   // fp16 Wk,Wq,Wv,Wr  [m][k]
__device__ __half g_Ctxh[BCC];           // ctx fp16
__device__ __half g_Mch [BCC];           // combined final A fp16 [m][k]
__device__ float  g_K   [BCHW];          // conv K fp32 [c][n]
__device__ float  g_Q   [BCHW];          // conv Q fp32 [c][n]
__device__ float  g_V   [BCHW];          // conv V fp32 [c][n]
__device__ float  g_G1  [BCHW];
__device__ float  g_G2  [BCHW];
__device__ float  g_Attm[BCC];
__device__ float  g_Meff[BCC];
__device__ float  g_Part[BCC * SPLITK];  // ONE reused split-K slab (L2-resident)
__device__ float  g_Bias[Cn];
__device__ float2 g_Stat[4 * Bn * Cn];   // [K, L0, L1, L2]

// ----------------------------- helpers -------------------------------------
__device__ __forceinline__ void mma16(float* c, const unsigned* a, const unsigned* b) {
    asm volatile(
        "mma.sync.aligned.m16n8k16.row.col.f32.f16.f16.f32 "
        "{%0,%1,%2,%3},{%4,%5,%6,%7},{%8,%9},{%0,%1,%2,%3};\n"
        : "+f"(c[0]), "+f"(c[1]), "+f"(c[2]), "+f"(c[3])
        : "r"(a[0]), "r"(a[1]), "r"(a[2]), "r"(a[3]),
          "r"(b[0]), "r"(b[1]));
}

__device__ __forceinline__ void ldsm4(unsigned& r0, unsigned& r1,
                                      unsigned& r2, unsigned& r3, uint32_t addr) {
    asm volatile("ldmatrix.sync.aligned.m8n8.x4.shared.b16 {%0,%1,%2,%3}, [%4];"
        : "=r"(r0), "=r"(r1), "=r"(r2), "=r"(r3) : "r"(addr));
}

__device__ __forceinline__ void cp16(uint32_t dst, const void* src) {
    asm volatile("cp.async.ca.shared.global [%0], [%1], 16;" :: "r"(dst), "l"(src));
}
#define CP_COMMIT() asm volatile("cp.async.commit_group;")
#define CP_WAIT1()  asm volatile("cp.async.wait_group 1;")
#define CP_WAIT0()  asm volatile("cp.async.wait_group 0;")

// fp16 tile: 128 rows x 32 k-halves, row stride 20 half2 (80 B)
#define HS2   20
#define TILE_U (128 * HS2)       // 2560 half2
#define TILE_B (TILE_U * 4)      // 10240 bytes

// ---------------------------------------------------------------------------
// scalar-LDS chunk (round-11 version) — used by gram_h (register-friendly)
// ---------------------------------------------------------------------------
__device__ __forceinline__ void gemm_chunk(const unsigned* Aq, const unsigned* Bq,
                                           int wm, int wn, int g, int t4,
                                           float acc[2][8][4])
{
    #pragma unroll
    for (int ks = 0; ks < 2; ks++) {
        const int k8 = ks * 8;
        unsigned af[2][4], bf[8][2];
        #pragma unroll
        for (int mi = 0; mi < 2; mi++) {
            int r = wm + mi * 16 + g;
            af[mi][0] = Aq[r * HS2 + k8 + t4];
            af[mi][1] = Aq[(r + 8) * HS2 + k8 + t4];
            af[mi][2] = Aq[r * HS2 + k8 + t4 + 4];
            af[mi][3] = Aq[(r + 8) * HS2 + k8 + t4 + 4];
        }
        #pragma unroll
        for (int ni = 0; ni < 8; ni++) {
            int nb = wn + ni * 8 + g;
            bf[ni][0] = Bq[nb * HS2 + k8 + t4];
            bf[ni][1] = Bq[nb * HS2 + k8 + t4 + 4];
        }
        #pragma unroll
        for (int mi = 0; mi < 2; mi++)
            #pragma unroll
            for (int ni = 0; ni < 8; ni++)
                mma16(acc[mi][ni], af[mi], bf[ni]);
    }
}

// ---------------------------------------------------------------------------
// LDSM chunk — used by gemm_h only (cheap cp.async producer).
// 12 LDSM.x4 + 32 HMMA per warp-chunk; conflict-free at 80B row stride.
// ---------------------------------------------------------------------------
__device__ __forceinline__ void gemm_chunk_ldsm(uint32_t aTile, uint32_t bTile,
                                                const uint32_t aOff[2],
                                                const uint32_t bOff[4],
                                                float acc[2][8][4])
{
    #pragma unroll
    for (int ks = 0; ks < 2; ks++) {
        const uint32_t ka = ks * 32;     // 8 half2 = 32 bytes per k16 step
        unsigned af[2][4], bf[8][2];
        #pragma unroll
        for (int mi = 0; mi < 2; mi++)
            ldsm4(af[mi][0], af[mi][1], af[mi][2], af[mi][3],
                  aTile + aOff[mi] + ka);
        #pragma unroll
        for (int p = 0; p < 4; p++)
            ldsm4(bf[2 * p][0], bf[2 * p][1], bf[2 * p + 1][0], bf[2 * p + 1][1],
                  bTile + bOff[p] + ka);
        #pragma unroll
        for (int mi = 0; mi < 2; mi++)
            #pragma unroll
            for (int ni = 0; ni < 8; ni++)
                mma16(acc[mi][ni], af[mi], bf[ni]);
    }
}

// ---------------------------------------------------------------------------
// gemm_h (fp16 NT, LDSM): Y[b,m,n] = sum_k A[(b),m,k] * B[b,n,k] (+ bias[m])
// ---------------------------------------------------------------------------
__global__ __launch_bounds__(256)
void gemm_h(const __half* __restrict__ A, size_t aStride,
            const __half* __restrict__ B, size_t bStride,
            const float* __restrict__ bias,
            float* __restrict__ Y, int ldY, size_t yStride)
{
    extern __shared__ unsigned sm[];
    uint32_t sb = (uint32_t)__cvta_generic_to_shared(sm);

    const int b  = blockIdx.z;
    const int m0 = blockIdx.y * 128;
    const int n0 = blockIdx.x * 128;
    const int t  = threadIdx.x;
    const __half* Ab = A + (size_t)b * aStride;
    const __half* Bb = B + (size_t)b * bStride;

    const int lane = t & 31, warp = t >> 5;
    const int wm = (warp & 3) * 32, wn = (warp >> 2) * 64;
    const int quad = lane >> 3, r8 = lane & 7;

    uint32_t aOff[2], bOff[4];
    #pragma unroll
    for (int mi = 0; mi < 2; mi++)
        aOff[mi] = (uint32_t)((wm + mi * 16 + 8 * (quad & 1) + r8) * 80 + (quad >> 1) * 16);
    #pragma unroll
    for (int p = 0; p < 4; p++)
        bOff[p] = (uint32_t)((wn + 16 * p + 8 * (quad >> 1) + r8) * 80 + (quad & 1) * 16);

    float acc[2][8][4] = {};

    auto issue = [&](int c, int st) {
        const int kc = c * 32;
        #pragma unroll
        for (int i = 0; i < 2; i++) {
            int s = t + i * 256;
            int row = s >> 2, f4 = s & 3;
            cp16(sb + (uint32_t)(st * TILE_U + row * HS2 + f4 * 4) * 4,
                 Ab + (size_t)(m0 + row) * Cn + kc + f4 * 8);
        }
        #pragma unroll
        for (int i = 0; i < 2; i++) {
            int s = t + i * 256;
            int row = s >> 2, f4 = s & 3;
            cp16(sb + (uint32_t)(2 * TILE_U + st * TILE_U + row * HS2 + f4 * 4) * 4,
                 Bb + (size_t)(n0 + row) * Cn + kc + f4 * 8);
        }
        CP_COMMIT();
    };

    issue(0, 0);
    const int NC = Cn / 32;
    for (int c = 0; c < NC; c++) {
        int st = c & 1;
        if (c + 1 < NC) { issue(c + 1, st ^ 1); CP_WAIT1(); }
        else            { CP_WAIT0(); }
        __syncthreads();
        gemm_chunk_ldsm(sb + st * TILE_B, sb + 2 * TILE_B + st * TILE_B,
                        aOff, bOff, acc);
        __syncthreads();
    }

    const int g = lane >> 2, t4 = lane & 3;
    float* Yb = Y + (size_t)b * yStride;
    #pragma unroll
    for (int mi = 0; mi < 2; mi++) {
        int r0 = m0 + wm + mi * 16 + g, r1 = r0 + 8;
        float bv0 = bias ? bias[r0] : 0.f;
        float bv1 = bias ? bias[r1] : 0.f;
        #pragma unroll
        for (int ni = 0; ni < 8; ni++) {
            int col = n0 + wn + ni * 8 + 2 * t4;
            float2 v0 = {acc[mi][ni][0] + bv0, acc[mi][ni][1] + bv0};
            float2 v1 = {acc[mi][ni][2] + bv1, acc[mi][ni][3] + bv1};
            *(float2*)&Yb[(size_t)r0 * ldY + col] = v0;
            *(float2*)&Yb[(size_t)r1 * ldY + col] = v1;
        }
    }
}

// ---------------------------------------------------------------------------
// gram_h (fp16 NT, split-K, on-the-fly softmax) — round-11 scalar-LDS loop.
// part[z,m,n] = sum_{k in split} softmax(A1-A2)[m,k] * (B1-B2)[n,k]
// grid (2, 2, Bn*SPLITK)
// ---------------------------------------------------------------------------
__global__ __launch_bounds__(256)
void gram_h(const float* __restrict__ A1, const float* __restrict__ A2,
            const float2* __restrict__ st,
            const float* __restrict__ B1, const float* __restrict__ B2,
            float* __restrict__ part)
{
    extern __shared__ unsigned sm[];
    unsigned* As = sm;
    unsigned* Bs = sm + 2 * TILE_U;

    const int z = blockIdx.z, b = z >> 3, s = z & 7;
    const int m0 = blockIdx.y * 128;
    const int n0 = blockIdx.x * 128;
    const int kb = s * (HWn / SPLITK);
    const int t = threadIdx.x;
    const size_t bo = (size_t)b * Cn * HWn;

    const int lane = t & 31, warp = t >> 5;
    const int wm = (warp & 3) * 32, wn = (warp >> 2) * 64;
    const int g = lane >> 2, t4 = lane & 3;
    const int lr = t >> 3, lc = (t & 7) * 4;

    const float2* stb = st + b * Cn;

    float acc[2][8][4] = {};
    float4 pa[4], pb[4];
    float2 ps[4];
    #pragma unroll
    for (int i = 0; i < 4; i++) ps[i] = stb[m0 + lr + i * 32];

    auto ldg = [&](int c) {
        const int kc = kb + c * 32;
        #pragma unroll
        for (int i = 0; i < 4; i++) {
            int row = lr + i * 32;
            size_t ia = bo + (size_t)(m0 + row) * HWn + kc + lc;
            pa[i] = *(const float4*)(A1 + ia);
            if (A2) {
                float4 q = *(const float4*)(A2 + ia);
                pa[i].x -= q.x; pa[i].y -= q.y; pa[i].z -= q.z; pa[i].w -= q.w;
            }
            size_t ib = bo + (size_t)(n0 + row) * HWn + kc + lc;
            pb[i] = *(const float4*)(B1 + ib);
            if (B2) {
                float4 q = *(const float4*)(B2 + ib);
                pb[i].x -= q.x; pb[i].y -= q.y; pb[i].z -= q.z; pb[i].w -= q.w;
            }
        }
    };
    auto sts = [&](int stg) {
        unsigned* Ab = As + stg * TILE_U;
        unsigned* Bb = Bs + stg * TILE_U;
        #pragma unroll
        for (int i = 0; i < 4; i++) {
            int row = lr + i * 32;
            float mx = ps[i].x, inv = ps[i].y;
            __half2 a0 = __floats2half2_rn(expf(pa[i].x - mx) * inv,
                                           expf(pa[i].y - mx) * inv);
            __half2 a1 = __floats2half2_rn(expf(pa[i].z - mx) * inv,
                                           expf(pa[i].w - mx) * inv);
            __half2 b0 = __floats2half2_rn(pb[i].x, pb[i].y);
            __half2 b1 = __floats2half2_rn(pb[i].z, pb[i].w);
            Ab[row * HS2 + (lc >> 1)]     = *(unsigned*)&a0;
            Ab[row * HS2 + (lc >> 1) + 1] = *(unsigned*)&a1;
            Bb[row * HS2 + (lc >> 1)]     = *(unsigned*)&b0;
            Bb[row * HS2 + (lc >> 1) + 1] = *(unsigned*)&b1;
        }
    };

    ldg(0);
    const int NC = (HWn / SPLITK) / 32;  // 16
    for (int c = 0; c < NC; c++) {
        int stg = c & 1;
        sts(stg);
        if (c + 1 < NC) ldg(c + 1);
        __syncthreads();
        gemm_chunk(As + stg * TILE_U, Bs + stg * TILE_U, wm, wn, g, t4, acc);
        // single sync per iter: buffer stg next overwritten at iter c+2,
        // after sync(c+1) which follows every warp's mma of iter c.
    }

    float* P = part + (size_t)z * Cn * Cn;
    #pragma unroll
    for (int mi = 0; mi < 2; mi++) {
        int r0 = m0 + wm + mi * 16 + g, r1 = r0 + 8;
        #pragma unroll
        for (int ni = 0; ni < 8; ni++) {
            int col = n0 + wn + ni * 8 + 2 * t4;
            *(float2*)&P[(size_t)r0 * Cn + col] = make_float2(acc[mi][ni][0], acc[mi][ni][1]);
            *(float2*)&P[(size_t)r1 * Cn + col] = make_float2(acc[mi][ni][2], acc[mi][ni][3]);
        }
    }
}

// ---------------------------------------------------------------------------
// prep_x: x fp32 [b][c][n] -> Xt fp16 [b][n][c].  grid (HW/64, C/64, B)
// ---------------------------------------------------------------------------
__global__ __launch_bounds__(256)
void prep_x(const float* __restrict__ x, __half* __restrict__ Xt)
{
    __shared__ float smt[64][65];
    const int b = blockIdx.z;
    const int c0 = blockIdx.y * 64;
    const int n0 = blockIdx.x * 64;
    const int t = threadIdx.x;
    const float* xb = x + (size_t)b * Cn * HWn;

    #pragma unroll
    for (int i = 0; i < 16; i++) {
        int idx = t + i * 256;
        int c = idx >> 6, nn = idx & 63;
        smt[c][nn] = xb[(size_t)(c0 + c) * HWn + n0 + nn];
    }
    __syncthreads();
    __half* ob = Xt + (size_t)b * HWn * Cn;
    #pragma unroll
    for (int i = 0; i < 2; i++) {
        int s = t + i * 256;
        int n = s >> 3, c8 = (s & 7) * 8;
        __half2 h[4];
        #pragma unroll
        for (int j = 0; j < 4; j++)
            h[j] = __floats2half2_rn(smt[c8 + 2 * j][n], smt[c8 + 2 * j + 1][n]);
        *(float4*)&ob[(size_t)(n0 + n) * Cn + c0 + c8] = *(float4*)h;
    }
}

// ---------------------------------------------------------------------------
// round4_h: fp16-round all 4 weight matrices + w0*br bias. 256 blocks.
// ---------------------------------------------------------------------------
__global__ __launch_bounds__(256)
void round4_h(const float* __restrict__ Wk, const float* __restrict__ Wq,
              const float* __restrict__ Wv, const float* __restrict__ Wr,
              const float* __restrict__ br, const float* __restrict__ wdw,
              __half* __restrict__ dst, float* __restrict__ bias)
{
    int i = blockIdx.x * 256 + threadIdx.x;
    dst[i]               = __float2half_rn(Wk[i]);
    dst[i + 1 * Cn * Cn] = __float2half_rn(Wq[i]);
    dst[i + 2 * Cn * Cn] = __float2half_rn(Wv[i]);
    dst[i + 3 * Cn * Cn] = __float2half_rn(Wr[i]);
    if (blockIdx.x == 0) bias[threadIdx.x] = wdw[2 * threadIdx.x] * br[threadIdx.x];
}

// ---------------------------------------------------------------------------
// row stats for K
// ---------------------------------------------------------------------------
__global__ __launch_bounds__(256)
void row_stats(const float* __restrict__ A, float2* __restrict__ st)
{
    __shared__ float red[256];
    const size_t base = (size_t)blockIdx.x * HWn;
    const int t = threadIdx.x;

    float v[16];
    float m = -INFINITY;
    #pragma unroll
    for (int i = 0; i < 16; i++) {
        v[i] = A[base + t + i * 256];
        m = fmaxf(m, v[i]);
    }
    red[t] = m; __syncthreads();
    for (int s = 128; s > 0; s >>= 1) {
        if (t < s) red[t] = fmaxf(red[t], red[t + s]);
        __syncthreads();
    }
    m = red[0]; __syncthreads();

    float sum = 0.f;
    #pragma unroll
    for (int i = 0; i < 16; i++) sum += expf(v[i] - m);
    red[t] = sum; __syncthreads();
    for (int s = 128; s > 0; s >>= 1) {
        if (t < s) red[t] += red[t + s];
        __syncthreads();
    }
    if (t == 0) st[blockIdx.x] = make_float2(m, 1.0f / red[0]);
}

// ---------------------------------------------------------------------------
// shuffle block reductions (256 threads); second stage reduces the 8 warp
// partials exactly once per 8-lane xor group (no scaling).
// ---------------------------------------------------------------------------
__device__ __forceinline__ float blk_max(float v, float* red, int t)
{
    #pragma unroll
    for (int o = 16; o > 0; o >>= 1)
        v = fmaxf(v, __shfl_xor_sync(0xffffffffu, v, o));
    if ((t & 31) == 0) red[t >> 5] = v;
    __syncthreads();
    if (t < 32) {
        float r = red[t & 7];
        #pragma unroll
        for (int o = 4; o > 0; o >>= 1)
            r = fmaxf(r, __shfl_xor_sync(0xffffffffu, r, o));
        if (t == 0) red[0] = r;
    }
    __syncthreads();
    float out = red[0];
    __syncthreads();
    return out;
}

__device__ __forceinline__ float blk_sum(float v, float* red, int t)
{
    #pragma unroll
    for (int o = 16; o > 0; o >>= 1)
        v += __shfl_xor_sync(0xffffffffu, v, o);
    if ((t & 31) == 0) red[t >> 5] = v;
    __syncthreads();
    if (t < 32) {
        float r = red[t & 7];
        #pragma unroll
        for (int o = 4; o > 0; o >>= 1)
            r += __shfl_xor_sync(0xffffffffu, r, o);
        if (t == 0) red[0] = r;
    }
    __syncthreads();
    float out = red[0];
    __syncthreads();
    return out;
}

// ---------------------------------------------------------------------------
// gauss_pyr: full Laplacian pyramid in ONE kernel. One block per (b,c) image.
// ---------------------------------------------------------------------------
struct G5 { float w[5]; };

__global__ __launch_bounds__(256)
void gauss_pyr(const float* __restrict__ x, float* __restrict__ G1o,
               float* __restrict__ G2o, G5 w3, G5 w5,
               float2* __restrict__ stL0, float2* __restrict__ stL1,
               float2* __restrict__ stL2)
{
    __shared__ float sa[68][72];
    __shared__ float sb_[68][72];
    __shared__ float red[8];

    const int img = blockIdx.x;
    const int t = threadIdx.x;
    const float* ip = x + (size_t)img * HWn;

    for (int i = t; i < 68 * 72; i += 256) {
        (&sa[0][0])[i] = 0.f;
        (&sb_[0][0])[i] = 0.f;
    }
    __syncthreads();

    float xv[16];
    #pragma unroll
    for (int i = 0; i < 16; i++) {
        int px = t + i * 256;
        xv[i] = ip[px];
        sa[(px >> 6) + 2][(px & 63) + 2] = xv[i];
    }
    __syncthreads();

    {
        float m = -INFINITY;
        #pragma unroll
        for (int i = 0; i < 16; i++) m = fmaxf(m, xv[i]);
        m = blk_max(m, red, t);
        float s = 0.f;
        #pragma unroll
        for (int i = 0; i < 16; i++) s += expf(xv[i] - m);
        s = blk_sum(s, red, t);
        if (t == 0) stL0[img] = make_float2(m, 1.0f / s);
    }

    #pragma unroll
    for (int i = 0; i < 16; i++) {
        int px = t + i * 256, y = (px >> 6) + 2, c = (px & 63) + 2;
        float a = 0.f;
        #pragma unroll
        for (int d = 0; d < 5; d++) a += w3.w[d] * sa[y][c + d - 2];
        sb_[y][c] = a;
    }
    __syncthreads();

    float g1[16];
    float* op1 = G1o + (size_t)img * HWn;
    #pragma unroll
    for (int i = 0; i < 16; i++) {
        int px = t + i * 256, y = (px >> 6) + 2, c = (px & 63) + 2;
        float a = 0.f;
        #pragma unroll
        for (int d = 0; d < 5; d++) a += w3.w[d] * sb_[y + d - 2][c];
        g1[i] = a;
        op1[px] = a;
    }

    {
        float m = -INFINITY;
        #pragma unroll
        for (int i = 0; i < 16; i++) m = fmaxf(m, xv[i] - g1[i]);
        m = blk_max(m, red, t);
        float s = 0.f;
        #pragma unroll
        for (int i = 0; i < 16; i++) s += expf(xv[i] - g1[i] - m);
        s = blk_sum(s, red, t);
        if (t == 0) stL1[img] = make_float2(m, 1.0f / s);
    }

    #pragma unroll
    for (int i = 0; i < 16; i++) {
        int px = t + i * 256;
        sa[(px >> 6) + 2][(px & 63) + 2] = g1[i];
    }
    __syncthreads();

    #pragma unroll
    for (int i = 0; i < 16; i++) {
        int px = t + i * 256, y = (px >> 6) + 2, c = (px & 63) + 2;
        float a = 0.f;
        #pragma unroll
        for (int d = 0; d < 5; d++) a += w5.w[d] * sa[y][c + d - 2];
        sb_[y][c] = a;
    }
    __syncthreads();

    float dv[16];
    float* op2 = G2o + (size_t)img * HWn;
    #pragma unroll
    for (int i = 0; i < 16; i++) {
        int px = t + i * 256, y = (px >> 6) + 2, c = (px & 63) + 2;
        float a = 0.f;
        #pragma unroll
        for (int d = 0; d < 5; d++) a += w5.w[d] * sb_[y + d - 2][c];
        op2[px] = a;
        dv[i] = g1[i] - a;
    }
    {
        float m = -INFINITY;
        #pragma unroll
        for (int i = 0; i < 16; i++) m = fmaxf(m, dv[i]);
        m = blk_max(m, red, t);
        float s = 0.f;
        #pragma unroll
        for (int i = 0; i < 16; i++) s += expf(dv[i] - m);
        s = blk_sum(s, red, t);
        if (t == 0) stL2[img] = make_float2(m, 1.0f / s);
    }
}

// ---------------------------------------------------------------------------
// softmax over channel axis (256) of Q fp32 [c][n]; writes Qt fp16 [n][c].
// ---------------------------------------------------------------------------
__global__ __launch_bounds__(256)
void softmax_c_qt(const float* __restrict__ Q, __half* __restrict__ Qt)
{
    extern __shared__ float smf[];
    const int P = 65;
    float* red = smf + 256 * P;
    const int blk = blockIdx.x;
    const int b = blk >> 6, n0 = (blk & 63) * 64;
    const float* base = Q + (size_t)b * Cn * HWn + n0;
    const int t = threadIdx.x, nl = t & 63, cs = t >> 6;

    #pragma unroll 4
    for (int i = 0; i < 64; i++) {
        int c = cs * 64 + i;
        smf[c * P + nl] = base[(size_t)c * HWn + nl];
    }
    __syncthreads();
    float m = -INFINITY;
    #pragma unroll 4
    for (int i = 0; i < 64; i++) m = fmaxf(m, smf[(cs * 64 + i) * P + nl]);
    red[cs * 64 + nl] = m;
    __syncthreads();
    if (t < 64)
        red[t] = fmaxf(fmaxf(red[t], red[64 + t]), fmaxf(red[128 + t], red[192 + t]));
    __syncthreads();
    m = red[nl];
    __syncthreads();
    float s = 0.f;
    #pragma unroll 4
    for (int i = 0; i < 64; i++) {
        int c = cs * 64 + i;
        float e = expf(smf[c * P + nl] - m);
        smf[c * P + nl] = e;
        s += e;
    }
    red[cs * 64 + nl] = s;
    __syncthreads();
    if (t < 64) red[t] = red[t] + red[64 + t] + red[128 + t] + red[192 + t];
    __syncthreads();
    float inv = 1.0f / red[nl];
    __half* ob = Qt + (size_t)b * HWn * Cn + (size_t)(n0 + nl) * Cn;
    #pragma unroll
    for (int i = 0; i < 64; i += 8) {
        int c = cs * 64 + i;
        __half2 h[4];
        #pragma unroll
        for (int j = 0; j < 4; j++)
            h[j] = __floats2half2_rn(smf[(c + 2 * j) * P + nl] * inv,
                                     smf[(c + 2 * j + 1) * P + nl] * inv);
        *(float4*)&ob[c] = *(float4*)h;
    }
}

// ---------------------------------------------------------------------------
// ctx reduce -> fp16
// ---------------------------------------------------------------------------
__global__ __launch_bounds__(256)
void reduce_ctx_h(const float* __restrict__ part, __half* __restrict__ ctx)
{
    const int e = blockIdx.x * 256 + threadIdx.x;
    const int b = e >> 16, r = e & 65535;
    float v = 0.f;
    #pragma unroll
    for (int s = 0; s < SPLITK; s++)
        v += part[((size_t)(b * SPLITK + s) << 16) + r];
    ctx[e] = __float2half_rn(v);
}

// ---------------------------------------------------------------------------
// row softmax (256) of split-K gram partials, accumulate into att (fp32)
// ---------------------------------------------------------------------------
__global__ __launch_bounds__(256)
void softmax_rows_accum(const float* __restrict__ part, float* __restrict__ att, int init)
{
    __shared__ float red[256];
    const int row = blockIdx.x;
    const int b = row >> 8, i = row & 255;
    const int t = threadIdx.x;

    float v = 0.f;
    size_t base = ((size_t)b * SPLITK << 16) + (size_t)i * Cn + t;
    #pragma unroll
    for (int s = 0; s < SPLITK; s++) v += part[base + ((size_t)s << 16)];

    red[t] = v; __syncthreads();
    for (int s = 128; s > 0; s >>= 1) {
        if (t < s) red[t] = fmaxf(red[t], red[t + s]);
        __syncthreads();
    }
    float m = red[0]; __syncthreads();
    float e = expf(v - m);
    red[t] = e; __syncthreads();
    for (int s = 128; s > 0; s >>= 1) {
        if (t < s) red[t] += red[t + s];
        __syncthreads();
    }
    float r = e / red[0];
    size_t o = (size_t)row * Cn + t;
    att[o] = init ? r : (att[o] + r);
}

// ---------------------------------------------------------------------------
// Mc[b][m][k] = fp16( w0[m]*Meff[b][m][k] + w1[m]*att[b][k][m] )
// ---------------------------------------------------------------------------
__global__ __launch_bounds__(256)
void combine_mc_h(const float* __restrict__ Meff, const float* __restrict__ att,
                  const float* __restrict__ wdw, __half* __restrict__ Mc)
{
    __shared__ float ts[32][33];
    const int b = blockIdx.z, m0 = blockIdx.y * 32, k0 = blockIdx.x * 32;
    const int tx = threadIdx.x & 31, ty = threadIdx.x >> 5;
    const float* attb = att + (size_t)b * Cn * Cn;

    #pragma unroll
    for (int j = 0; j < 4; j++)
        ts[ty + j * 8][tx] = attb[(size_t)(k0 + ty + j * 8) * Cn + m0 + tx];
    __syncthreads();

    const float* mb = Meff + (size_t)b * Cn * Cn;
    __half* ob = Mc + (size_t)b * Cn * Cn;
    #pragma unroll
    for (int j = 0; j < 4; j++) {
        int m = m0 + ty + j * 8, k = k0 + tx;
        float w0 = wdw[2 * m], w1 = wdw[2 * m + 1];
        ob[(size_t)m * Cn + k] =
            __float2half_rn(w0 * mb[(size_t)m * Cn + k] + w1 * ts[tx][ty + j * 8]);
    }
}

// ---------------------------------------------------------------------------
// host
// ---------------------------------------------------------------------------
static void make_gauss1d(int ksize, double sigma, float* w)
{
    double g[5], s = 0.0;
    for (int i = 0; i < ksize; i++) {
        double d = (double)i - (ksize - 1) / 2.0;
        g[i] = exp(-(d * d) / (2.0 * sigma * sigma));
        s += g[i];
    }
    for (int i = 0; i < ksize; i++) w[i] = (float)(g[i] / s);
}

extern "C" void kernel_launch(void* const* d_in, const int* in_sizes, int n_in,
                              void* d_out, int out_size)
{
    (void)in_sizes; (void)n_in; (void)out_size;
    const float* x   = (const float*)d_in[0];
    const float* Wk  = (const float*)d_in[1];
    const float* bk  = (const float*)d_in[2];
    const float* Wq  = (const float*)d_in[3];
    const float* bq  = (const float*)d_in[4];
    const float* Wv  = (const float*)d_in[5];
    const float* bv  = (const float*)d_in[6];
    const float* Wr  = (const float*)d_in[7];
    const float* br  = (const float*)d_in[8];
    const float* wdw = (const float*)d_in[9];
    float* out = (float*)d_out;

    __half *gXt, *gQt, *gWh, *gCtxh, *gMch;
    float *gK, *gQ, *gV, *gG1, *gG2, *gAttm, *gMeff, *gPart, *gBias;
    float2* gSt;
    cudaGetSymbolAddress((void**)&gXt,   g_Xt);
    cudaGetSymbolAddress((void**)&gQt,   g_Qt);
    cudaGetSymbolAddress((void**)&gWh,   g_Wh);
    cudaGetSymbolAddress((void**)&gCtxh, g_Ctxh);
    cudaGetSymbolAddress((void**)&gMch,  g_Mch);
    cudaGetSymbolAddress((void**)&gK,    g_K);
    cudaGetSymbolAddress((void**)&gQ,    g_Q);
    cudaGetSymbolAddress((void**)&gV,    g_V);
    cudaGetSymbolAddress((void**)&gG1,   g_G1);
    cudaGetSymbolAddress((void**)&gG2,   g_G2);
    cudaGetSymbolAddress((void**)&gAttm, g_Attm);
    cudaGetSymbolAddress((void**)&gMeff, g_Meff);
    cudaGetSymbolAddress((void**)&gPart, g_Part);
    cudaGetSymbolAddress((void**)&gBias, g_Bias);
    cudaGetSymbolAddress((void**)&gSt,   g_Stat);

    float2* stK  = gSt + 0 * Bn * Cn;
    float2* stL0 = gSt + 1 * Bn * Cn;
    float2* stL1 = gSt + 2 * Bn * Cn;
    float2* stL2 = gSt + 3 * Bn * Cn;

    const int SM_GEMM = 4 * TILE_B;              // 40960
    const int SM_SMC  = (256 * 65 + 512) * 4;    // 68608
    cudaFuncSetAttribute(gemm_h,        cudaFuncAttributeMaxDynamicSharedMemorySize, SM_GEMM);
    cudaFuncSetAttribute(gram_h,        cudaFuncAttributeMaxDynamicSharedMemorySize, SM_GEMM);
    cudaFuncSetAttribute(softmax_c_qt,  cudaFuncAttributeMaxDynamicSharedMemorySize, SM_SMC);

    const double SIGMA = 1.6;
    const double S_VAL = cbrt(2.0);
    G5 g3 = {}, g5 = {};
    float t3[5];
    make_gauss1d(3, SIGMA, t3);
    g3.w[0] = 0.f; g3.w[1] = t3[0]; g3.w[2] = t3[1]; g3.w[3] = t3[2]; g3.w[4] = 0.f;
    make_gauss1d(5, SIGMA * S_VAL, g5.w);

    dim3 gConv(HWn / 128, Cn / 128, Bn);          // (32, 2, 8)
    dim3 gGram(Cn / 128, Cn / 128, Bn * SPLITK);  // (2, 2, 64)
    dim3 gMeffG(Cn / 128, Cn / 128, Bn);          // (2, 2, 8)
    dim3 gComb(Cn / 32, Cn / 32, Bn);             // (8, 8, 8)
    dim3 gPrep(HWn / 64, Cn / 64, Bn);            // (64, 4, 8)

    // prep: weights fp16 + bias fold; x transpose fp16
    round4_h<<<Cn * Cn / 256, 256>>>(Wk, Wq, Wv, Wr, br, wdw, gWh, gBias);
    prep_x<<<gPrep, 256>>>(x, gXt);

    // 1x1 convs: Y = W @ Xt^T
    gemm_h<<<gConv, 256, SM_GEMM>>>(gWh + 0 * Cn * Cn, 0, gXt, (size_t)HWn * Cn,
                                    bk, gK, HWn, (size_t)Cn * HWn);
    gemm_h<<<gConv, 256, SM_GEMM>>>(gWh + 1 * Cn * Cn, 0, gXt, (size_t)HWn * Cn,
                                    bq, gQ, HWn, (size_t)Cn * HWn);
    gemm_h<<<gConv, 256, SM_GEMM>>>(gWh + 2 * Cn * Cn, 0, gXt, (size_t)HWn * Cn,
                                    bv, gV, HWn, (size_t)Cn * HWn);

    // stats + channel softmax (Q -> Qt fp16)
    row_stats<<<Bn * Cn, 256>>>(gK, stK);
    softmax_c_qt<<<Bn * 64, 256, SM_SMC>>>(gQ, gQt);

    // fused Gaussian pyramid + all Laplacian stats (ONE launch)
    gauss_pyr<<<Bn * Cn, 256>>>(x, gG1, gG2, g3, g5, stL0, stL1, stL2);

    // efficient attention: ctx = softmax(K) @ V^T
    gram_h<<<gGram, 256, SM_GEMM>>>(gK, nullptr, stK, gV, nullptr, gPart);
    reduce_ctx_h<<<BCC / 256, 256>>>(gPart, gCtxh);

    // Meff = Wr @ ctx^T
    gemm_h<<<gMeffG, 256, SM_GEMM>>>(gWh + 3 * (size_t)Cn * Cn, 0,
                                     gCtxh, (size_t)Cn * Cn,
                                     nullptr, gMeff, Cn, (size_t)Cn * Cn);

    // channel attention: 3 Laplacian levels (single reused part buffer)
    gram_h<<<gGram, 256, SM_GEMM>>>(x, nullptr, stL0, x, nullptr, gPart);
    softmax_rows_accum<<<Bn * Cn, 256>>>(gPart, gAttm, 1);

    gram_h<<<gGram, 256, SM_GEMM>>>(x, gG1, stL1, x, gG1, gPart);
    softmax_rows_accum<<<Bn * Cn, 256>>>(gPart, gAttm, 0);

    gram_h<<<gGram, 256, SM_GEMM>>>(gG1, gG2, stL2, gG1, gG2, gPart);
    softmax_rows_accum<<<Bn * Cn, 256>>>(gPart, gAttm, 0);

    // fold: out = Mc @ Qt^T + w0*br
    combine_mc_h<<<gComb, 256>>>(gMeff, gAttm, wdw, gMch);
    gemm_h<<<gConv, 256, SM_GEMM>>>(gMch, (size_t)Cn * Cn,
                                    gQt, (size_t)HWn * Cn,
                                    gBias, out, HWn, (size_t)Cn * HWn);
}

// round 14
// speedup vs baseline: 1.3209x; 1.0846x over previous
#include <cuda_runtime.h>
#include <cuda_fp16.h>
#include <math.h>
#include <stdint.h>

// ---------------------------------------------------------------------------
// EfficientFrequencyAttention  B=8, C=256, H=W=64
// Round 14: 3-stage cp.async pipeline in gemm family (1 sync/chunk),
//           3 convs merged into one launch. gram_h unchanged (round-11 loop).
// ---------------------------------------------------------------------------
#define Bn  8
#define Cn  256
#define HWn 4096
#define BCHW (Bn*Cn*HWn)   // 8,388,608
#define BCC  (Bn*Cn*Cn)    // 524,288
#define SPLITK 8

// ----------------------------- scratch (static, no allocation) -------------
__device__ __half g_Xt  [BCHW];          // x transposed fp16: [b][n][c]
__device__ __half g_Qt  [BCHW];          // softmax_c(Q) transposed fp16: [b][n][c]
__device__ __half g_Wh  [4 * Cn * Cn];   // fp16 Wk,Wq,Wv,Wr  [m][k]
__device__ __half g_Ctxh[BCC];           // ctx fp16
__device__ __half g_Mch [BCC];           // combined final A fp16 [m][k]
__device__ float  g_K   [BCHW];          // conv K fp32 [c][n]
__device__ float  g_Q   [BCHW];          // conv Q fp32 [c][n]
__device__ float  g_V   [BCHW];          // conv V fp32 [c][n]
__device__ float  g_G1  [BCHW];
__device__ float  g_G2  [BCHW];
__device__ float  g_Attm[BCC];
__device__ float  g_Meff[BCC];
__device__ float  g_Part[BCC * SPLITK];  // ONE reused split-K slab (L2-resident)
__device__ float  g_Bias[Cn];
__device__ float2 g_Stat[4 * Bn * Cn];   // [K, L0, L1, L2]

// ----------------------------- helpers -------------------------------------
__device__ __forceinline__ void mma16(float* c, const unsigned* a, const unsigned* b) {
    asm volatile(
        "mma.sync.aligned.m16n8k16.row.col.f32.f16.f16.f32 "
        "{%0,%1,%2,%3},{%4,%5,%6,%7},{%8,%9},{%0,%1,%2,%3};\n"
        : "+f"(c[0]), "+f"(c[1]), "+f"(c[2]), "+f"(c[3])
        : "r"(a[0]), "r"(a[1]), "r"(a[2]), "r"(a[3]),
          "r"(b[0]), "r"(b[1]));
}

__device__ __forceinline__ void ldsm4(unsigned& r0, unsigned& r1,
                                      unsigned& r2, unsigned& r3, uint32_t addr) {
    asm volatile("ldmatrix.sync.aligned.m8n8.x4.shared.b16 {%0,%1,%2,%3}, [%4];"
        : "=r"(r0), "=r"(r1), "=r"(r2), "=r"(r3) : "r"(addr));
}

__device__ __forceinline__ void cp16(uint32_t dst, const void* src) {
    asm volatile("cp.async.ca.shared.global [%0], [%1], 16;" :: "r"(dst), "l"(src));
}
#define CP_COMMIT() asm volatile("cp.async.commit_group;")
#define CP_WAIT1()  asm volatile("cp.async.wait_group 1;")
#define CP_WAIT0()  asm volatile("cp.async.wait_group 0;")

// fp16 tile: 128 rows x 32 k-halves, row stride 20 half2 (80 B)
#define HS2   20
#define TILE_U (128 * HS2)        // 2560 half2
#define TILE_B (TILE_U * 4)       // 10240 bytes
#define STG_B  (2 * TILE_B)       // A+B tiles per pipeline stage (20480 B)
#define SM_GEMM3 (3 * STG_B)      // 61440 B  (3-stage pipeline)

// ---------------------------------------------------------------------------
// scalar-LDS chunk (round-11) — used by gram_h (register-friendly producer)
// ---------------------------------------------------------------------------
__device__ __forceinline__ void gemm_chunk(const unsigned* Aq, const unsigned* Bq,
                                           int wm, int wn, int g, int t4,
                                           float acc[2][8][4])
{
    #pragma unroll
    for (int ks = 0; ks < 2; ks++) {
        const int k8 = ks * 8;
        unsigned af[2][4], bf[8][2];
        #pragma unroll
        for (int mi = 0; mi < 2; mi++) {
            int r = wm + mi * 16 + g;
            af[mi][0] = Aq[r * HS2 + k8 + t4];
            af[mi][1] = Aq[(r + 8) * HS2 + k8 + t4];
            af[mi][2] = Aq[r * HS2 + k8 + t4 + 4];
            af[mi][3] = Aq[(r + 8) * HS2 + k8 + t4 + 4];
        }
        #pragma unroll
        for (int ni = 0; ni < 8; ni++) {
            int nb = wn + ni * 8 + g;
            bf[ni][0] = Bq[nb * HS2 + k8 + t4];
            bf[ni][1] = Bq[nb * HS2 + k8 + t4 + 4];
        }
        #pragma unroll
        for (int mi = 0; mi < 2; mi++)
            #pragma unroll
            for (int ni = 0; ni < 8; ni++)
                mma16(acc[mi][ni], af[mi], bf[ni]);
    }
}

// ---------------------------------------------------------------------------
// LDSM chunk — gemm family (cheap cp.async producer).
// 12 LDSM.x4 + 32 HMMA per warp-chunk; conflict-free at 80B row stride.
// ---------------------------------------------------------------------------
__device__ __forceinline__ void gemm_chunk_ldsm(uint32_t aTile, uint32_t bTile,
                                                const uint32_t aOff[2],
                                                const uint32_t bOff[4],
                                                float acc[2][8][4])
{
    #pragma unroll
    for (int ks = 0; ks < 2; ks++) {
        const uint32_t ka = ks * 32;
        unsigned af[2][4], bf[8][2];
        #pragma unroll
        for (int mi = 0; mi < 2; mi++)
            ldsm4(af[mi][0], af[mi][1], af[mi][2], af[mi][3],
                  aTile + aOff[mi] + ka);
        #pragma unroll
        for (int p = 0; p < 4; p++)
            ldsm4(bf[2 * p][0], bf[2 * p][1], bf[2 * p + 1][0], bf[2 * p + 1][1],
                  bTile + bOff[p] + ka);
        #pragma unroll
        for (int mi = 0; mi < 2; mi++)
            #pragma unroll
            for (int ni = 0; ni < 8; ni++)
                mma16(acc[mi][ni], af[mi], bf[ni]);
    }
}

// ---------------------------------------------------------------------------
// 3-stage pipelined GEMM body (shared by gemm_h / conv3_h).
// At iter c: stage c%3 ready (waited), stage c+1 in flight, issue c+2.
// One __syncthreads per chunk: sync-then-issue makes reuse of stage
// (c+2)%3 == (c-1)%3 safe (fully read before the barrier).
// ---------------------------------------------------------------------------
template <typename IssueFn>
__device__ __forceinline__ void gemm_body3(IssueFn issue, uint32_t sb,
                                           const uint32_t aOff[2],
                                           const uint32_t bOff[4],
                                           int NC, float acc[2][8][4])
{
    issue(0, 0);
    issue(1, 1);
    for (int c = 0; c < NC; c++) {
        if (c == NC - 1) { CP_WAIT0(); }
        else             { CP_WAIT1(); }
        __syncthreads();
        if (c + 2 < NC) issue(c + 2, (c + 2) % 3);
        const uint32_t stg = (uint32_t)(c % 3) * STG_B;
        gemm_chunk_ldsm(sb + stg, sb + stg + TILE_B, aOff, bOff, acc);
    }
}

// ---------------------------------------------------------------------------
// conv3_h: all three 1x1 convs in ONE launch (grid y: wsel*2 + m-tile).
// Y[b,m,n] = sum_k W[wsel][m,k] * Xt[b,n,k] + bias[m]   (fp32 out)
// grid (32, 6, 8) = 1536 blocks.
// ---------------------------------------------------------------------------
__global__ __launch_bounds__(256)
void conv3_h(const __half* __restrict__ Wh, const __half* __restrict__ Xt,
             const float* __restrict__ bk, const float* __restrict__ bq,
             const float* __restrict__ bv,
             float* __restrict__ Ko, float* __restrict__ Qo, float* __restrict__ Vo)
{
    extern __shared__ unsigned sm[];
    uint32_t sb = (uint32_t)__cvta_generic_to_shared(sm);

    const int wsel = blockIdx.y >> 1;
    const int m0 = (blockIdx.y & 1) * 128;
    const int b  = blockIdx.z;
    const int n0 = blockIdx.x * 128;
    const int t  = threadIdx.x;
    const __half* Ab = Wh + (size_t)wsel * Cn * Cn;
    const __half* Bb = Xt + (size_t)b * HWn * Cn;
    const float* bias = wsel == 0 ? bk : (wsel == 1 ? bq : bv);
    float* Y = (wsel == 0 ? Ko : (wsel == 1 ? Qo : Vo)) + (size_t)b * Cn * HWn;

    const int lane = t & 31, warp = t >> 5;
    const int wm = (warp & 3) * 32, wn = (warp >> 2) * 64;
    const int quad = lane >> 3, r8 = lane & 7;

    uint32_t aOff[2], bOff[4];
    #pragma unroll
    for (int mi = 0; mi < 2; mi++)
        aOff[mi] = (uint32_t)((wm + mi * 16 + 8 * (quad & 1) + r8) * 80 + (quad >> 1) * 16);
    #pragma unroll
    for (int p = 0; p < 4; p++)
        bOff[p] = (uint32_t)((wn + 16 * p + 8 * (quad >> 1) + r8) * 80 + (quad & 1) * 16);

    float acc[2][8][4] = {};

    auto issue = [&](int c, int stg) {
        const int kc = c * 32;
        const uint32_t base = sb + (uint32_t)stg * STG_B;
        #pragma unroll
        for (int i = 0; i < 2; i++) {
            int s = t + i * 256;
            int row = s >> 2, f4 = s & 3;
            cp16(base + (uint32_t)(row * HS2 + f4 * 4) * 4,
                 Ab + (size_t)(m0 + row) * Cn + kc + f4 * 8);
        }
        #pragma unroll
        for (int i = 0; i < 2; i++) {
            int s = t + i * 256;
            int row = s >> 2, f4 = s & 3;
            cp16(base + TILE_B + (uint32_t)(row * HS2 + f4 * 4) * 4,
                 Bb + (size_t)(n0 + row) * Cn + kc + f4 * 8);
        }
        CP_COMMIT();
    };

    gemm_body3(issue, sb, aOff, bOff, Cn / 32, acc);

    const int g = lane >> 2, t4 = lane & 3;
    #pragma unroll
    for (int mi = 0; mi < 2; mi++) {
        int r0 = m0 + wm + mi * 16 + g, r1 = r0 + 8;
        float bv0 = bias[r0], bv1 = bias[r1];
        #pragma unroll
        for (int ni = 0; ni < 8; ni++) {
            int col = n0 + wn + ni * 8 + 2 * t4;
            float2 v0 = {acc[mi][ni][0] + bv0, acc[mi][ni][1] + bv0};
            float2 v1 = {acc[mi][ni][2] + bv1, acc[mi][ni][3] + bv1};
            *(float2*)&Y[(size_t)r0 * HWn + col] = v0;
            *(float2*)&Y[(size_t)r1 * HWn + col] = v1;
        }
    }
}

// ---------------------------------------------------------------------------
// gemm_h (fp16 NT, LDSM, 3-stage): Y[b,m,n] = sum_k A[(b),m,k]*B[b,n,k] (+bias)
// ---------------------------------------------------------------------------
__global__ __launch_bounds__(256)
void gemm_h(const __half* __restrict__ A, size_t aStride,
            const __half* __restrict__ B, size_t bStride,
            const float* __restrict__ bias,
            float* __restrict__ Y, int ldY, size_t yStride)
{
    extern __shared__ unsigned sm[];
    uint32_t sb = (uint32_t)__cvta_generic_to_shared(sm);

    const int b  = blockIdx.z;
    const int m0 = blockIdx.y * 128;
    const int n0 = blockIdx.x * 128;
    const int t  = threadIdx.x;
    const __half* Ab = A + (size_t)b * aStride;
    const __half* Bb = B + (size_t)b * bStride;

    const int lane = t & 31, warp = t >> 5;
    const int wm = (warp & 3) * 32, wn = (warp >> 2) * 64;
    const int quad = lane >> 3, r8 = lane & 7;

    uint32_t aOff[2], bOff[4];
    #pragma unroll
    for (int mi = 0; mi < 2; mi++)
        aOff[mi] = (uint32_t)((wm + mi * 16 + 8 * (quad & 1) + r8) * 80 + (quad >> 1) * 16);
    #pragma unroll
    for (int p = 0; p < 4; p++)
        bOff[p] = (uint32_t)((wn + 16 * p + 8 * (quad >> 1) + r8) * 80 + (quad & 1) * 16);

    float acc[2][8][4] = {};

    auto issue = [&](int c, int stg) {
        const int kc = c * 32;
        const uint32_t base = sb + (uint32_t)stg * STG_B;
        #pragma unroll
        for (int i = 0; i < 2; i++) {
            int s = t + i * 256;
            int row = s >> 2, f4 = s & 3;
            cp16(base + (uint32_t)(row * HS2 + f4 * 4) * 4,
                 Ab + (size_t)(m0 + row) * Cn + kc + f4 * 8);
        }
        #pragma unroll
        for (int i = 0; i < 2; i++) {
            int s = t + i * 256;
            int row = s >> 2, f4 = s & 3;
            cp16(base + TILE_B + (uint32_t)(row * HS2 + f4 * 4) * 4,
                 Bb + (size_t)(n0 + row) * Cn + kc + f4 * 8);
        }
        CP_COMMIT();
    };

    gemm_body3(issue, sb, aOff, bOff, Cn / 32, acc);

    const int g = lane >> 2, t4 = lane & 3;
    float* Yb = Y + (size_t)b * yStride;
    #pragma unroll
    for (int mi = 0; mi < 2; mi++) {
        int r0 = m0 + wm + mi * 16 + g, r1 = r0 + 8;
        float bv0 = bias ? bias[r0] : 0.f;
        float bv1 = bias ? bias[r1] : 0.f;
        #pragma unroll
        for (int ni = 0; ni < 8; ni++) {
            int col = n0 + wn + ni * 8 + 2 * t4;
            float2 v0 = {acc[mi][ni][0] + bv0, acc[mi][ni][1] + bv0};
            float2 v1 = {acc[mi][ni][2] + bv1, acc[mi][ni][3] + bv1};
            *(float2*)&Yb[(size_t)r0 * ldY + col] = v0;
            *(float2*)&Yb[(size_t)r1 * ldY + col] = v1;
        }
    }
}

// ---------------------------------------------------------------------------
// gram_h (fp16 NT, split-K, on-the-fly softmax) — round-11 scalar-LDS loop.
// part[z,m,n] = sum_{k in split} softmax(A1-A2)[m,k] * (B1-B2)[n,k]
// grid (2, 2, Bn*SPLITK)
// ---------------------------------------------------------------------------
__global__ __launch_bounds__(256)
void gram_h(const float* __restrict__ A1, const float* __restrict__ A2,
            const float2* __restrict__ st,
            const float* __restrict__ B1, const float* __restrict__ B2,
            float* __restrict__ part)
{
    extern __shared__ unsigned sm[];
    unsigned* As = sm;
    unsigned* Bs = sm + 2 * TILE_U;

    const int z = blockIdx.z, b = z >> 3, s = z & 7;
    const int m0 = blockIdx.y * 128;
    const int n0 = blockIdx.x * 128;
    const int kb = s * (HWn / SPLITK);
    const int t = threadIdx.x;
    const size_t bo = (size_t)b * Cn * HWn;

    const int lane = t & 31, warp = t >> 5;
    const int wm = (warp & 3) * 32, wn = (warp >> 2) * 64;
    const int g = lane >> 2, t4 = lane & 3;
    const int lr = t >> 3, lc = (t & 7) * 4;

    const float2* stb = st + b * Cn;

    float acc[2][8][4] = {};
    float4 pa[4], pb[4];
    float2 ps[4];
    #pragma unroll
    for (int i = 0; i < 4; i++) ps[i] = stb[m0 + lr + i * 32];

    auto ldg = [&](int c) {
        const int kc = kb + c * 32;
        #pragma unroll
        for (int i = 0; i < 4; i++) {
            int row = lr + i * 32;
            size_t ia = bo + (size_t)(m0 + row) * HWn + kc + lc;
            pa[i] = *(const float4*)(A1 + ia);
            if (A2) {
                float4 q = *(const float4*)(A2 + ia);
                pa[i].x -= q.x; pa[i].y -= q.y; pa[i].z -= q.z; pa[i].w -= q.w;
            }
            size_t ib = bo + (size_t)(n0 + row) * HWn + kc + lc;
            pb[i] = *(const float4*)(B1 + ib);
            if (B2) {
                float4 q = *(const float4*)(B2 + ib);
                pb[i].x -= q.x; pb[i].y -= q.y; pb[i].z -= q.z; pb[i].w -= q.w;
            }
        }
    };
    auto sts = [&](int stg) {
        unsigned* Ab = As + stg * TILE_U;
        unsigned* Bb = Bs + stg * TILE_U;
        #pragma unroll
        for (int i = 0; i < 4; i++) {
            int row = lr + i * 32;
            float mx = ps[i].x, inv = ps[i].y;
            __half2 a0 = __floats2half2_rn(expf(pa[i].x - mx) * inv,
                                           expf(pa[i].y - mx) * inv);
            __half2 a1 = __floats2half2_rn(expf(pa[i].z - mx) * inv,
                                           expf(pa[i].w - mx) * inv);
            __half2 b0 = __floats2half2_rn(pb[i].x, pb[i].y);
            __half2 b1 = __floats2half2_rn(pb[i].z, pb[i].w);
            Ab[row * HS2 + (lc >> 1)]     = *(unsigned*)&a0;
            Ab[row * HS2 + (lc >> 1) + 1] = *(unsigned*)&a1;
            Bb[row * HS2 + (lc >> 1)]     = *(unsigned*)&b0;
            Bb[row * HS2 + (lc >> 1) + 1] = *(unsigned*)&b1;
        }
    };

    ldg(0);
    const int NC = (HWn / SPLITK) / 32;  // 16
    for (int c = 0; c < NC; c++) {
        int stg = c & 1;
        sts(stg);
        if (c + 1 < NC) ldg(c + 1);
        __syncthreads();
        gemm_chunk(As + stg * TILE_U, Bs + stg * TILE_U, wm, wn, g, t4, acc);
        // single sync per iter: buffer stg next overwritten at iter c+2,
        // after sync(c+1) which follows every warp's mma of iter c.
    }

    float* P = part + (size_t)z * Cn * Cn;
    #pragma unroll
    for (int mi = 0; mi < 2; mi++) {
        int r0 = m0 + wm + mi * 16 + g, r1 = r0 + 8;
        #pragma unroll
        for (int ni = 0; ni < 8; ni++) {
            int col = n0 + wn + ni * 8 + 2 * t4;
            *(float2*)&P[(size_t)r0 * Cn + col] = make_float2(acc[mi][ni][0], acc[mi][ni][1]);
            *(float2*)&P[(size_t)r1 * Cn + col] = make_float2(acc[mi][ni][2], acc[mi][ni][3]);
        }
    }
}

// ---------------------------------------------------------------------------
// prep_x: x fp32 [b][c][n] -> Xt fp16 [b][n][c].  grid (HW/64, C/64, B)
// ---------------------------------------------------------------------------
__global__ __launch_bounds__(256)
void prep_x(const float* __restrict__ x, __half* __restrict__ Xt)
{
    __shared__ float smt[64][65];
    const int b = blockIdx.z;
    const int c0 = blockIdx.y * 64;
    const int n0 = blockIdx.x * 64;
    const int t = threadIdx.x;
    const float* xb = x + (size_t)b * Cn * HWn;

    #pragma unroll
    for (int i = 0; i < 16; i++) {
        int idx = t + i * 256;
        int c = idx >> 6, nn = idx & 63;
        smt[c][nn] = xb[(size_t)(c0 + c) * HWn + n0 + nn];
    }
    __syncthreads();
    __half* ob = Xt + (size_t)b * HWn * Cn;
    #pragma unroll
    for (int i = 0; i < 2; i++) {
        int s = t + i * 256;
        int n = s >> 3, c8 = (s & 7) * 8;
        __half2 h[4];
        #pragma unroll
        for (int j = 0; j < 4; j++)
            h[j] = __floats2half2_rn(smt[c8 + 2 * j][n], smt[c8 + 2 * j + 1][n]);
        *(float4*)&ob[(size_t)(n0 + n) * Cn + c0 + c8] = *(float4*)h;
    }
}

// ---------------------------------------------------------------------------
// round4_h: fp16-round all 4 weight matrices + w0*br bias. 256 blocks.
// ---------------------------------------------------------------------------
__global__ __launch_bounds__(256)
void round4_h(const float* __restrict__ Wk, const float* __restrict__ Wq,
              const float* __restrict__ Wv, const float* __restrict__ Wr,
              const float* __restrict__ br, const float* __restrict__ wdw,
              __half* __restrict__ dst, float* __restrict__ bias)
{
    int i = blockIdx.x * 256 + threadIdx.x;
    dst[i]               = __float2half_rn(Wk[i]);
    dst[i + 1 * Cn * Cn] = __float2half_rn(Wq[i]);
    dst[i + 2 * Cn * Cn] = __float2half_rn(Wv[i]);
    dst[i + 3 * Cn * Cn] = __float2half_rn(Wr[i]);
    if (blockIdx.x == 0) bias[threadIdx.x] = wdw[2 * threadIdx.x] * br[threadIdx.x];
}

// ---------------------------------------------------------------------------
// row stats for K
// ---------------------------------------------------------------------------
__global__ __launch_bounds__(256)
void row_stats(const float* __restrict__ A, float2* __restrict__ st)
{
    __shared__ float red[256];
    const size_t base = (size_t)blockIdx.x * HWn;
    const int t = threadIdx.x;

    float v[16];
    float m = -INFINITY;
    #pragma unroll
    for (int i = 0; i < 16; i++) {
        v[i] = A[base + t + i * 256];
        m = fmaxf(m, v[i]);
    }
    red[t] = m; __syncthreads();
    for (int s = 128; s > 0; s >>= 1) {
        if (t < s) red[t] = fmaxf(red[t], red[t + s]);
        __syncthreads();
    }
    m = red[0]; __syncthreads();

    float sum = 0.f;
    #pragma unroll
    for (int i = 0; i < 16; i++) sum += expf(v[i] - m);
    red[t] = sum; __syncthreads();
    for (int s = 128; s > 0; s >>= 1) {
        if (t < s) red[t] += red[t + s];
        __syncthreads();
    }
    if (t == 0) st[blockIdx.x] = make_float2(m, 1.0f / red[0]);
}

// ---------------------------------------------------------------------------
// shuffle block reductions (256 threads); exact (no scaling).
// ---------------------------------------------------------------------------
__device__ __forceinline__ float blk_max(float v, float* red, int t)
{
    #pragma unroll
    for (int o = 16; o > 0; o >>= 1)
        v = fmaxf(v, __shfl_xor_sync(0xffffffffu, v, o));
    if ((t & 31) == 0) red[t >> 5] = v;
    __syncthreads();
    if (t < 32) {
        float r = red[t & 7];
        #pragma unroll
        for (int o = 4; o > 0; o >>= 1)
            r = fmaxf(r, __shfl_xor_sync(0xffffffffu, r, o));
        if (t == 0) red[0] = r;
    }
    __syncthreads();
    float out = red[0];
    __syncthreads();
    return out;
}

__device__ __forceinline__ float blk_sum(float v, float* red, int t)
{
    #pragma unroll
    for (int o = 16; o > 0; o >>= 1)
        v += __shfl_xor_sync(0xffffffffu, v, o);
    if ((t & 31) == 0) red[t >> 5] = v;
    __syncthreads();
    if (t < 32) {
        float r = red[t & 7];
        #pragma unroll
        for (int o = 4; o > 0; o >>= 1)
            r += __shfl_xor_sync(0xffffffffu, r, o);
        if (t == 0) red[0] = r;
    }
    __syncthreads();
    float out = red[0];
    __syncthreads();
    return out;
}

// ---------------------------------------------------------------------------
// gauss_pyr: full Laplacian pyramid in ONE kernel. One block per (b,c) image.
// ---------------------------------------------------------------------------
struct G5 { float w[5]; };

__global__ __launch_bounds__(256)
void gauss_pyr(const float* __restrict__ x, float* __restrict__ G1o,
               float* __restrict__ G2o, G5 w3, G5 w5,
               float2* __restrict__ stL0, float2* __restrict__ stL1,
               float2* __restrict__ stL2)
{
    __shared__ float sa[68][72];
    __shared__ float sb_[68][72];
    __shared__ float red[8];

    const int img = blockIdx.x;
    const int t = threadIdx.x;
    const float* ip = x + (size_t)img * HWn;

    for (int i = t; i < 68 * 72; i += 256) {
        (&sa[0][0])[i] = 0.f;
        (&sb_[0][0])[i] = 0.f;
    }
    __syncthreads();

    float xv[16];
    #pragma unroll
    for (int i = 0; i < 16; i++) {
        int px = t + i * 256;
        xv[i] = ip[px];
        sa[(px >> 6) + 2][(px & 63) + 2] = xv[i];
    }
    __syncthreads();

    {
        float m = -INFINITY;
        #pragma unroll
        for (int i = 0; i < 16; i++) m = fmaxf(m, xv[i]);
        m = blk_max(m, red, t);
        float s = 0.f;
        #pragma unroll
        for (int i = 0; i < 16; i++) s += expf(xv[i] - m);
        s = blk_sum(s, red, t);
        if (t == 0) stL0[img] = make_float2(m, 1.0f / s);
    }

    #pragma unroll
    for (int i = 0; i < 16; i++) {
        int px = t + i * 256, y = (px >> 6) + 2, c = (px & 63) + 2;
        float a = 0.f;
        #pragma unroll
        for (int d = 0; d < 5; d++) a += w3.w[d] * sa[y][c + d - 2];
        sb_[y][c] = a;
    }
    __syncthreads();

    float g1[16];
    float* op1 = G1o + (size_t)img * HWn;
    #pragma unroll
    for (int i = 0; i < 16; i++) {
        int px = t + i * 256, y = (px >> 6) + 2, c = (px & 63) + 2;
        float a = 0.f;
        #pragma unroll
        for (int d = 0; d < 5; d++) a += w3.w[d] * sb_[y + d - 2][c];
        g1[i] = a;
        op1[px] = a;
    }

    {
        float m = -INFINITY;
        #pragma unroll
        for (int i = 0; i < 16; i++) m = fmaxf(m, xv[i] - g1[i]);
        m = blk_max(m, red, t);
        float s = 0.f;
        #pragma unroll
        for (int i = 0; i < 16; i++) s += expf(xv[i] - g1[i] - m);
        s = blk_sum(s, red, t);
        if (t == 0) stL1[img] = make_float2(m, 1.0f / s);
    }

    #pragma unroll
    for (int i = 0; i < 16; i++) {
        int px = t + i * 256;
        sa[(px >> 6) + 2][(px & 63) + 2] = g1[i];
    }
    __syncthreads();

    #pragma unroll
    for (int i = 0; i < 16; i++) {
        int px = t + i * 256, y = (px >> 6) + 2, c = (px & 63) + 2;
        float a = 0.f;
        #pragma unroll
        for (int d = 0; d < 5; d++) a += w5.w[d] * sa[y][c + d - 2];
        sb_[y][c] = a;
    }
    __syncthreads();

    float dv[16];
    float* op2 = G2o + (size_t)img * HWn;
    #pragma unroll
    for (int i = 0; i < 16; i++) {
        int px = t + i * 256, y = (px >> 6) + 2, c = (px & 63) + 2;
        float a = 0.f;
        #pragma unroll
        for (int d = 0; d < 5; d++) a += w5.w[d] * sb_[y + d - 2][c];
        op2[px] = a;
        dv[i] = g1[i] - a;
    }
    {
        float m = -INFINITY;
        #pragma unroll
        for (int i = 0; i < 16; i++) m = fmaxf(m, dv[i]);
        m = blk_max(m, red, t);
        float s = 0.f;
        #pragma unroll
        for (int i = 0; i < 16; i++) s += expf(dv[i] - m);
        s = blk_sum(s, red, t);
        if (t == 0) stL2[img] = make_float2(m, 1.0f / s);
    }
}

// ---------------------------------------------------------------------------
// softmax over channel axis (256) of Q fp32 [c][n]; writes Qt fp16 [n][c].
// ---------------------------------------------------------------------------
__global__ __launch_bounds__(256)
void softmax_c_qt(const float* __restrict__ Q, __half* __restrict__ Qt)
{
    extern __shared__ float smf[];
    const int P = 65;
    float* red = smf + 256 * P;
    const int blk = blockIdx.x;
    const int b = blk >> 6, n0 = (blk & 63) * 64;
    const float* base = Q + (size_t)b * Cn * HWn + n0;
    const int t = threadIdx.x, nl = t & 63, cs = t >> 6;

    #pragma unroll 4
    for (int i = 0; i < 64; i++) {
        int c = cs * 64 + i;
        smf[c * P + nl] = base[(size_t)c * HWn + nl];
    }
    __syncthreads();
    float m = -INFINITY;
    #pragma unroll 4
    for (int i = 0; i < 64; i++) m = fmaxf(m, smf[(cs * 64 + i) * P + nl]);
    red[cs * 64 + nl] = m;
    __syncthreads();
    if (t < 64)
        red[t] = fmaxf(fmaxf(red[t], red[64 + t]), fmaxf(red[128 + t], red[192 + t]));
    __syncthreads();
    m = red[nl];
    __syncthreads();
    float s = 0.f;
    #pragma unroll 4
    for (int i = 0; i < 64; i++) {
        int c = cs * 64 + i;
        float e = expf(smf[c * P + nl] - m);
        smf[c * P + nl] = e;
        s += e;
    }
    red[cs * 64 + nl] = s;
    __syncthreads();
    if (t < 64) red[t] = red[t] + red[64 + t] + red[128 + t] + red[192 + t];
    __syncthreads();
    float inv = 1.0f / red[nl];
    __half* ob = Qt + (size_t)b * HWn * Cn + (size_t)(n0 + nl) * Cn;
    #pragma unroll
    for (int i = 0; i < 64; i += 8) {
        int c = cs * 64 + i;
        __half2 h[4];
        #pragma unroll
        for (int j = 0; j < 4; j++)
            h[j] = __floats2half2_rn(smf[(c + 2 * j) * P + nl] * inv,
                                     smf[(c + 2 * j + 1) * P + nl] * inv);
        *(float4*)&ob[c] = *(float4*)h;
    }
}

// ---------------------------------------------------------------------------
// ctx reduce -> fp16
// ---------------------------------------------------------------------------
__global__ __launch_bounds__(256)
void reduce_ctx_h(const float* __restrict__ part, __half* __restrict__ ctx)
{
    const int e = blockIdx.x * 256 + threadIdx.x;
    const int b = e >> 16, r = e & 65535;
    float v = 0.f;
    #pragma unroll
    for (int s = 0; s < SPLITK; s++)
        v += part[((size_t)(b * SPLITK + s) << 16) + r];
    ctx[e] = __float2half_rn(v);
}

// ---------------------------------------------------------------------------
// row softmax (256) of split-K gram partials, accumulate into att (fp32)
// ---------------------------------------------------------------------------
__global__ __launch_bounds__(256)
void softmax_rows_accum(const float* __restrict__ part, float* __restrict__ att, int init)
{
    __shared__ float red[256];
    const int row = blockIdx.x;
    const int b = row >> 8, i = row & 255;
    const int t = threadIdx.x;

    float v = 0.f;
    size_t base = ((size_t)b * SPLITK << 16) + (size_t)i * Cn + t;
    #pragma unroll
    for (int s = 0; s < SPLITK; s++) v += part[base + ((size_t)s << 16)];

    red[t] = v; __syncthreads();
    for (int s = 128; s > 0; s >>= 1) {
        if (t < s) red[t] = fmaxf(red[t], red[t + s]);
        __syncthreads();
    }
    float m = red[0]; __syncthreads();
    float e = expf(v - m);
    red[t] = e; __syncthreads();
    for (int s = 128; s > 0; s >>= 1) {
        if (t < s) red[t] += red[t + s];
        __syncthreads();
    }
    float r = e / red[0];
    size_t o = (size_t)row * Cn + t;
    att[o] = init ? r : (att[o] + r);
}

// ---------------------------------------------------------------------------
// Mc[b][m][k] = fp16( w0[m]*Meff[b][m][k] + w1[m]*att[b][k][m] )
// ---------------------------------------------------------------------------
__global__ __launch_bounds__(256)
void combine_mc_h(const float* __restrict__ Meff, const float* __restrict__ att,
                  const float* __restrict__ wdw, __half* __restrict__ Mc)
{
    __shared__ float ts[32][33];
    const int b = blockIdx.z, m0 = blockIdx.y * 32, k0 = blockIdx.x * 32;
    const int tx = threadIdx.x & 31, ty = threadIdx.x >> 5;
    const float* attb = att + (size_t)b * Cn * Cn;

    #pragma unroll
    for (int j = 0; j < 4; j++)
        ts[ty + j * 8][tx] = attb[(size_t)(k0 + ty + j * 8) * Cn + m0 + tx];
    __syncthreads();

    const float* mb = Meff + (size_t)b * Cn * Cn;
    __half* ob = Mc + (size_t)b * Cn * Cn;
    #pragma unroll
    for (int j = 0; j < 4; j++) {
        int m = m0 + ty + j * 8, k = k0 + tx;
        float w0 = wdw[2 * m], w1 = wdw[2 * m + 1];
        ob[(size_t)m * Cn + k] =
            __float2half_rn(w0 * mb[(size_t)m * Cn + k] + w1 * ts[tx][ty + j * 8]);
    }
}

// ---------------------------------------------------------------------------
// host
// ---------------------------------------------------------------------------
static void make_gauss1d(int ksize, double sigma, float* w)
{
    double g[5], s = 0.0;
    for (int i = 0; i < ksize; i++) {
        double d = (double)i - (ksize - 1) / 2.0;
        g[i] = exp(-(d * d) / (2.0 * sigma * sigma));
        s += g[i];
    }
    for (int i = 0; i < ksize; i++) w[i] = (float)(g[i] / s);
}

extern "C" void kernel_launch(void* const* d_in, const int* in_sizes, int n_in,
                              void* d_out, int out_size)
{
    (void)in_sizes; (void)n_in; (void)out_size;
    const float* x   = (const float*)d_in[0];
    const float* Wk  = (const float*)d_in[1];
    const float* bk  = (const float*)d_in[2];
    const float* Wq  = (const float*)d_in[3];
    const float* bq  = (const float*)d_in[4];
    const float* Wv  = (const float*)d_in[5];
    const float* bv  = (const float*)d_in[6];
    const float* Wr  = (const float*)d_in[7];
    const float* br  = (const float*)d_in[8];
    const float* wdw = (const float*)d_in[9];
    float* out = (float*)d_out;

    __half *gXt, *gQt, *gWh, *gCtxh, *gMch;
    float *gK, *gQ, *gV, *gG1, *gG2, *gAttm, *gMeff, *gPart, *gBias;
    float2* gSt;
    cudaGetSymbolAddress((void**)&gXt,   g_Xt);
    cudaGetSymbolAddress((void**)&gQt,   g_Qt);
    cudaGetSymbolAddress((void**)&gWh,   g_Wh);
    cudaGetSymbolAddress((void**)&gCtxh, g_Ctxh);
    cudaGetSymbolAddress((void**)&gMch,  g_Mch);
    cudaGetSymbolAddress((void**)&gK,    g_K);
    cudaGetSymbolAddress((void**)&gQ,    g_Q);
    cudaGetSymbolAddress((void**)&gV,    g_V);
    cudaGetSymbolAddress((void**)&gG1,   g_G1);
    cudaGetSymbolAddress((void**)&gG2,   g_G2);
    cudaGetSymbolAddress((void**)&gAttm, g_Attm);
    cudaGetSymbolAddress((void**)&gMeff, g_Meff);
    cudaGetSymbolAddress((void**)&gPart, g_Part);
    cudaGetSymbolAddress((void**)&gBias, g_Bias);
    cudaGetSymbolAddress((void**)&gSt,   g_Stat);

    float2* stK  = gSt + 0 * Bn * Cn;
    float2* stL0 = gSt + 1 * Bn * Cn;
    float2* stL1 = gSt + 2 * Bn * Cn;
    float2* stL2 = gSt + 3 * Bn * Cn;

    const int SM_GRAM = 4 * TILE_B;              // 40960 (2-stage, gram_h)
    const int SM_SMC  = (256 * 65 + 512) * 4;    // 68608
    cudaFuncSetAttribute(conv3_h,       cudaFuncAttributeMaxDynamicSharedMemorySize, SM_GEMM3);
    cudaFuncSetAttribute(gemm_h,        cudaFuncAttributeMaxDynamicSharedMemorySize, SM_GEMM3);
    cudaFuncSetAttribute(gram_h,        cudaFuncAttributeMaxDynamicSharedMemorySize, SM_GRAM);
    cudaFuncSetAttribute(softmax_c_qt,  cudaFuncAttributeMaxDynamicSharedMemorySize, SM_SMC);

    const double SIGMA = 1.6;
    const double S_VAL = cbrt(2.0);
    G5 g3 = {}, g5 = {};
    float t3[5];
    make_gauss1d(3, SIGMA, t3);
    g3.w[0] = 0.f; g3.w[1] = t3[0]; g3.w[2] = t3[1]; g3.w[3] = t3[2]; g3.w[4] = 0.f;
    make_gauss1d(5, SIGMA * S_VAL, g5.w);

    dim3 gConv3(HWn / 128, 6, Bn);                // (32, 6, 8) = 1536 blocks
    dim3 gGram(Cn / 128, Cn / 128, Bn * SPLITK);  // (2, 2, 64)
    dim3 gMeffG(Cn / 128, Cn / 128, Bn);          // (2, 2, 8)
    dim3 gFinal(HWn / 128, Cn / 128, Bn);         // (32, 2, 8)
    dim3 gComb(Cn / 32, Cn / 32, Bn);             // (8, 8, 8)
    dim3 gPrep(HWn / 64, Cn / 64, Bn);            // (64, 4, 8)

    // prep: weights fp16 + bias fold; x transpose fp16
    round4_h<<<Cn * Cn / 256, 256>>>(Wk, Wq, Wv, Wr, br, wdw, gWh, gBias);
    prep_x<<<gPrep, 256>>>(x, gXt);

    // all three 1x1 convs in ONE launch
    conv3_h<<<gConv3, 256, SM_GEMM3>>>(gWh, gXt, bk, bq, bv, gK, gQ, gV);

    // stats + channel softmax (Q -> Qt fp16)
    row_stats<<<Bn * Cn, 256>>>(gK, stK);
    softmax_c_qt<<<Bn * 64, 256, SM_SMC>>>(gQ, gQt);

    // fused Gaussian pyramid + all Laplacian stats (ONE launch)
    gauss_pyr<<<Bn * Cn, 256>>>(x, gG1, gG2, g3, g5, stL0, stL1, stL2);

    // efficient attention: ctx = softmax(K) @ V^T
    gram_h<<<gGram, 256, SM_GRAM>>>(gK, nullptr, stK, gV, nullptr, gPart);
    reduce_ctx_h<<<BCC / 256, 256>>>(gPart, gCtxh);

    // Meff = Wr @ ctx^T
    gemm_h<<<gMeffG, 256, SM_GEMM3>>>(gWh + 3 * (size_t)Cn * Cn, 0,
                                      gCtxh, (size_t)Cn * Cn,
                                      nullptr, gMeff, Cn, (size_t)Cn * Cn);

    // channel attention: 3 Laplacian levels (single reused part buffer)
    gram_h<<<gGram, 256, SM_GRAM>>>(x, nullptr, stL0, x, nullptr, gPart);
    softmax_rows_accum<<<Bn * Cn, 256>>>(gPart, gAttm, 1);

    gram_h<<<gGram, 256, SM_GRAM>>>(x, gG1, stL1, x, gG1, gPart);
    softmax_rows_accum<<<Bn * Cn, 256>>>(gPart, gAttm, 0);

    gram_h<<<gGram, 256, SM_GRAM>>>(gG1, gG2, stL2, gG1, gG2, gPart);
    softmax_rows_accum<<<Bn * Cn, 256>>>(gPart, gAttm, 0);

    // fold: out = Mc @ Qt^T + w0*br
    combine_mc_h<<<gComb, 256>>>(gMeff, gAttm, wdw, gMch);
    gemm_h<<<gFinal, 256, SM_GEMM3>>>(gMch, (size_t)Cn * Cn,
                                      gQt, (size_t)HWn * Cn,
                                      gBias, out, HWn, (size_t)Cn * HWn);
}

// round 15
// speedup vs baseline: 1.5108x; 1.1438x over previous
#include <cuda_runtime.h>
#include <cuda_fp16.h>
#include <math.h>
#include <stdint.h>

// ---------------------------------------------------------------------------
// EfficientFrequencyAttention  B=8, C=256, H=W=64
// Round 15: gram operands pre-materialized as fp16 (by gauss_pyr / krow_h /
//           conv3_h); all 4 grams run the 3-stage LDSM GEMM path (gram_g).
// ---------------------------------------------------------------------------
#define Bn  8
#define Cn  256
#define HWn 4096
#define BCHW (Bn*Cn*HWn)   // 8,388,608
#define BCC  (Bn*Cn*Cn)    // 524,288
#define SPLITK 8

// ----------------------------- scratch (static, no allocation) -------------
__device__ __half g_Xt  [BCHW];          // x transposed fp16: [b][n][c]
__device__ __half g_Qt  [BCHW];          // softmax_c(Q) transposed fp16: [b][n][c]
__device__ __half g_Wh  [4 * Cn * Cn];   // fp16 Wk,Wq,Wv,Wr  [m][k]
__device__ __half g_Ctxh[BCC];           // ctx fp16
__device__ __half g_Mch [BCC];           // combined final A fp16 [m][k]
__device__ float  g_K   [BCHW];          // conv K fp32 [c][n]
__device__ float  g_Q   [BCHW];          // conv Q fp32 [c][n]
__device__ __half g_Kh  [BCHW];          // softmax(K) fp16
__device__ __half g_Vh  [BCHW];          // V fp16
__device__ __half g_A1h [BCHW];          // softmax(x) fp16
__device__ __half g_B1h [BCHW];          // x fp16
__device__ __half g_A2h [BCHW];          // softmax(x-G1) fp16
__device__ __half g_B2h [BCHW];          // (x-G1) fp16
__device__ __half g_A3h [BCHW];          // softmax(G1-G2) fp16
__device__ __half g_B3h [BCHW];          // (G1-G2) fp16
__device__ float  g_Attm[BCC];
__device__ float  g_Meff[BCC];
__device__ float  g_Part[BCC * SPLITK];  // ONE reused split-K slab (L2-resident)
__device__ float  g_Bias[Cn];

// ----------------------------- helpers -------------------------------------
__device__ __forceinline__ void mma16(float* c, const unsigned* a, const unsigned* b) {
    asm volatile(
        "mma.sync.aligned.m16n8k16.row.col.f32.f16.f16.f32 "
        "{%0,%1,%2,%3},{%4,%5,%6,%7},{%8,%9},{%0,%1,%2,%3};\n"
        : "+f"(c[0]), "+f"(c[1]), "+f"(c[2]), "+f"(c[3])
        : "r"(a[0]), "r"(a[1]), "r"(a[2]), "r"(a[3]),
          "r"(b[0]), "r"(b[1]));
}

__device__ __forceinline__ void ldsm4(unsigned& r0, unsigned& r1,
                                      unsigned& r2, unsigned& r3, uint32_t addr) {
    asm volatile("ldmatrix.sync.aligned.m8n8.x4.shared.b16 {%0,%1,%2,%3}, [%4];"
        : "=r"(r0), "=r"(r1), "=r"(r2), "=r"(r3) : "r"(addr));
}

__device__ __forceinline__ void cp16(uint32_t dst, const void* src) {
    asm volatile("cp.async.ca.shared.global [%0], [%1], 16;" :: "r"(dst), "l"(src));
}
#define CP_COMMIT() asm volatile("cp.async.commit_group;")
#define CP_WAIT1()  asm volatile("cp.async.wait_group 1;")
#define CP_WAIT0()  asm volatile("cp.async.wait_group 0;")

// fp16 tile: 128 rows x 32 k-halves, row stride 20 half2 (80 B)
#define HS2   20
#define TILE_U (128 * HS2)        // 2560 half2
#define TILE_B (TILE_U * 4)       // 10240 bytes
#define STG_B  (2 * TILE_B)       // A+B tiles per pipeline stage (20480 B)
#define SM_GEMM3 (3 * STG_B)      // 61440 B

// ---------------------------------------------------------------------------
// LDSM chunk: 12 LDSM.x4 + 32 HMMA per warp-chunk; conflict-free @ 80B stride.
// ---------------------------------------------------------------------------
__device__ __forceinline__ void gemm_chunk_ldsm(uint32_t aTile, uint32_t bTile,
                                                const uint32_t aOff[2],
                                                const uint32_t bOff[4],
                                                float acc[2][8][4])
{
    #pragma unroll
    for (int ks = 0; ks < 2; ks++) {
        const uint32_t ka = ks * 32;
        unsigned af[2][4], bf[8][2];
        #pragma unroll
        for (int mi = 0; mi < 2; mi++)
            ldsm4(af[mi][0], af[mi][1], af[mi][2], af[mi][3],
                  aTile + aOff[mi] + ka);
        #pragma unroll
        for (int p = 0; p < 4; p++)
            ldsm4(bf[2 * p][0], bf[2 * p][1], bf[2 * p + 1][0], bf[2 * p + 1][1],
                  bTile + bOff[p] + ka);
        #pragma unroll
        for (int mi = 0; mi < 2; mi++)
            #pragma unroll
            for (int ni = 0; ni < 8; ni++)
                mma16(acc[mi][ni], af[mi], bf[ni]);
    }
}

// 3-stage pipelined body: wait(c) / in-flight(c+1) / issue(c+2); 1 sync/chunk.
template <typename IssueFn>
__device__ __forceinline__ void gemm_body3(IssueFn issue, uint32_t sb,
                                           const uint32_t aOff[2],
                                           const uint32_t bOff[4],
                                           int NC, float acc[2][8][4])
{
    issue(0, 0);
    issue(1, 1);
    for (int c = 0; c < NC; c++) {
        if (c == NC - 1) { CP_WAIT0(); }
        else             { CP_WAIT1(); }
        __syncthreads();
        if (c + 2 < NC) issue(c + 2, (c + 2) % 3);
        const uint32_t stg = (uint32_t)(c % 3) * STG_B;
        gemm_chunk_ldsm(sb + stg, sb + stg + TILE_B, aOff, bOff, acc);
    }
}

__device__ __forceinline__ void frag_offsets(int lane, int wm, int wn,
                                             uint32_t aOff[2], uint32_t bOff[4])
{
    const int quad = lane >> 3, r8 = lane & 7;
    #pragma unroll
    for (int mi = 0; mi < 2; mi++)
        aOff[mi] = (uint32_t)((wm + mi * 16 + 8 * (quad & 1) + r8) * 80 + (quad >> 1) * 16);
    #pragma unroll
    for (int p = 0; p < 4; p++)
        bOff[p] = (uint32_t)((wn + 16 * p + 8 * (quad >> 1) + r8) * 80 + (quad & 1) * 16);
}

// ---------------------------------------------------------------------------
// conv3_h: all three 1x1 convs in ONE launch. K,Q -> fp32; V -> fp16.
// grid (32, 6, 8)
// ---------------------------------------------------------------------------
__global__ __launch_bounds__(256)
void conv3_h(const __half* __restrict__ Wh, const __half* __restrict__ Xt,
             const float* __restrict__ bk, const float* __restrict__ bq,
             const float* __restrict__ bv,
             float* __restrict__ Ko, float* __restrict__ Qo,
             __half* __restrict__ Vh)
{
    extern __shared__ unsigned sm[];
    uint32_t sb = (uint32_t)__cvta_generic_to_shared(sm);

    const int wsel = blockIdx.y >> 1;
    const int m0 = (blockIdx.y & 1) * 128;
    const int b  = blockIdx.z;
    const int n0 = blockIdx.x * 128;
    const int t  = threadIdx.x;
    const __half* Ab = Wh + (size_t)wsel * Cn * Cn;
    const __half* Bb = Xt + (size_t)b * HWn * Cn;
    const float* bias = wsel == 0 ? bk : (wsel == 1 ? bq : bv);

    const int lane = t & 31, warp = t >> 5;
    const int wm = (warp & 3) * 32, wn = (warp >> 2) * 64;
    uint32_t aOff[2], bOff[4];
    frag_offsets(lane, wm, wn, aOff, bOff);

    float acc[2][8][4] = {};

    auto issue = [&](int c, int stg) {
        const int kc = c * 32;
        const uint32_t base = sb + (uint32_t)stg * STG_B;
        #pragma unroll
        for (int i = 0; i < 2; i++) {
            int s = t + i * 256;
            int row = s >> 2, f4 = s & 3;
            cp16(base + (uint32_t)(row * HS2 + f4 * 4) * 4,
                 Ab + (size_t)(m0 + row) * Cn + kc + f4 * 8);
        }
        #pragma unroll
        for (int i = 0; i < 2; i++) {
            int s = t + i * 256;
            int row = s >> 2, f4 = s & 3;
            cp16(base + TILE_B + (uint32_t)(row * HS2 + f4 * 4) * 4,
                 Bb + (size_t)(n0 + row) * Cn + kc + f4 * 8);
        }
        CP_COMMIT();
    };

    gemm_body3(issue, sb, aOff, bOff, Cn / 32, acc);

    const int g = lane >> 2, t4 = lane & 3;
    #pragma unroll
    for (int mi = 0; mi < 2; mi++) {
        int r0 = m0 + wm + mi * 16 + g, r1 = r0 + 8;
        float bv0 = bias[r0], bv1 = bias[r1];
        #pragma unroll
        for (int ni = 0; ni < 8; ni++) {
            int col = n0 + wn + ni * 8 + 2 * t4;
            float2 v0 = {acc[mi][ni][0] + bv0, acc[mi][ni][1] + bv0};
            float2 v1 = {acc[mi][ni][2] + bv1, acc[mi][ni][3] + bv1};
            if (wsel < 2) {
                float* Y = (wsel == 0 ? Ko : Qo) + (size_t)b * Cn * HWn;
                *(float2*)&Y[(size_t)r0 * HWn + col] = v0;
                *(float2*)&Y[(size_t)r1 * HWn + col] = v1;
            } else {
                __half* Yh = Vh + (size_t)b * Cn * HWn;
                __half2 h0 = __floats2half2_rn(v0.x, v0.y);
                __half2 h1 = __floats2half2_rn(v1.x, v1.y);
                *(__half2*)&Yh[(size_t)r0 * HWn + col] = h0;
                *(__half2*)&Yh[(size_t)r1 * HWn + col] = h1;
            }
        }
    }
}

// ---------------------------------------------------------------------------
// gemm_h (fp16 NT, LDSM, 3-stage, ld = Cn): Meff + final GEMM.
// ---------------------------------------------------------------------------
__global__ __launch_bounds__(256)
void gemm_h(const __half* __restrict__ A, size_t aStride,
            const __half* __restrict__ B, size_t bStride,
            const float* __restrict__ bias,
            float* __restrict__ Y, int ldY, size_t yStride)
{
    extern __shared__ unsigned sm[];
    uint32_t sb = (uint32_t)__cvta_generic_to_shared(sm);

    const int b  = blockIdx.z;
    const int m0 = blockIdx.y * 128;
    const int n0 = blockIdx.x * 128;
    const int t  = threadIdx.x;
    const __half* Ab = A + (size_t)b * aStride;
    const __half* Bb = B + (size_t)b * bStride;

    const int lane = t & 31, warp = t >> 5;
    const int wm = (warp & 3) * 32, wn = (warp >> 2) * 64;
    uint32_t aOff[2], bOff[4];
    frag_offsets(lane, wm, wn, aOff, bOff);

    float acc[2][8][4] = {};

    auto issue = [&](int c, int stg) {
        const int kc = c * 32;
        const uint32_t base = sb + (uint32_t)stg * STG_B;
        #pragma unroll
        for (int i = 0; i < 2; i++) {
            int s = t + i * 256;
            int row = s >> 2, f4 = s & 3;
            cp16(base + (uint32_t)(row * HS2 + f4 * 4) * 4,
                 Ab + (size_t)(m0 + row) * Cn + kc + f4 * 8);
        }
        #pragma unroll
        for (int i = 0; i < 2; i++) {
            int s = t + i * 256;
            int row = s >> 2, f4 = s & 3;
            cp16(base + TILE_B + (uint32_t)(row * HS2 + f4 * 4) * 4,
                 Bb + (size_t)(n0 + row) * Cn + kc + f4 * 8);
        }
        CP_COMMIT();
    };

    gemm_body3(issue, sb, aOff, bOff, Cn / 32, acc);

    const int g = lane >> 2, t4 = lane & 3;
    float* Yb = Y + (size_t)b * yStride;
    #pragma unroll
    for (int mi = 0; mi < 2; mi++) {
        int r0 = m0 + wm + mi * 16 + g, r1 = r0 + 8;
        float bv0 = bias ? bias[r0] : 0.f;
        float bv1 = bias ? bias[r1] : 0.f;
        #pragma unroll
        for (int ni = 0; ni < 8; ni++) {
            int col = n0 + wn + ni * 8 + 2 * t4;
            float2 v0 = {acc[mi][ni][0] + bv0, acc[mi][ni][1] + bv0};
            float2 v1 = {acc[mi][ni][2] + bv1, acc[mi][ni][3] + bv1};
            *(float2*)&Yb[(size_t)r0 * ldY + col] = v0;
            *(float2*)&Yb[(size_t)r1 * ldY + col] = v1;
        }
    }
}

// ---------------------------------------------------------------------------
// gram_g (fp16 NT, split-K, ld = HWn, 3-stage LDSM):
//   part[z,m,n] = sum_{k in split} A[b,m,k] * B[b,n,k]
// grid (2, 2, Bn*SPLITK)
// ---------------------------------------------------------------------------
__global__ __launch_bounds__(256)
void gram_g(const __half* __restrict__ A, const __half* __restrict__ B,
            float* __restrict__ part)
{
    extern __shared__ unsigned sm[];
    uint32_t sb = (uint32_t)__cvta_generic_to_shared(sm);

    const int z = blockIdx.z, b = z >> 3, s = z & 7;
    const int m0 = blockIdx.y * 128;
    const int n0 = blockIdx.x * 128;
    const int kb = s * (HWn / SPLITK);
    const int t = threadIdx.x;
    const __half* Ab = A + (size_t)b * Cn * HWn;
    const __half* Bb = B + (size_t)b * Cn * HWn;

    const int lane = t & 31, warp = t >> 5;
    const int wm = (warp & 3) * 32, wn = (warp >> 2) * 64;
    uint32_t aOff[2], bOff[4];
    frag_offsets(lane, wm, wn, aOff, bOff);

    float acc[2][8][4] = {};

    auto issue = [&](int c, int stg) {
        const int kc = kb + c * 32;
        const uint32_t base = sb + (uint32_t)stg * STG_B;
        #pragma unroll
        for (int i = 0; i < 2; i++) {
            int s2 = t + i * 256;
            int row = s2 >> 2, f4 = s2 & 3;
            cp16(base + (uint32_t)(row * HS2 + f4 * 4) * 4,
                 Ab + (size_t)(m0 + row) * HWn + kc + f4 * 8);
        }
        #pragma unroll
        for (int i = 0; i < 2; i++) {
            int s2 = t + i * 256;
            int row = s2 >> 2, f4 = s2 & 3;
            cp16(base + TILE_B + (uint32_t)(row * HS2 + f4 * 4) * 4,
                 Bb + (size_t)(n0 + row) * HWn + kc + f4 * 8);
        }
        CP_COMMIT();
    };

    gemm_body3(issue, sb, aOff, bOff, (HWn / SPLITK) / 32, acc);

    const int g = lane >> 2, t4 = lane & 3;
    float* P = part + (size_t)z * Cn * Cn;
    #pragma unroll
    for (int mi = 0; mi < 2; mi++) {
        int r0 = m0 + wm + mi * 16 + g, r1 = r0 + 8;
        #pragma unroll
        for (int ni = 0; ni < 8; ni++) {
            int col = n0 + wn + ni * 8 + 2 * t4;
            *(float2*)&P[(size_t)r0 * Cn + col] = make_float2(acc[mi][ni][0], acc[mi][ni][1]);
            *(float2*)&P[(size_t)r1 * Cn + col] = make_float2(acc[mi][ni][2], acc[mi][ni][3]);
        }
    }
}

// ---------------------------------------------------------------------------
// prep_x: x fp32 [b][c][n] -> Xt fp16 [b][n][c].  grid (HW/64, C/64, B)
// ---------------------------------------------------------------------------
__global__ __launch_bounds__(256)
void prep_x(const float* __restrict__ x, __half* __restrict__ Xt)
{
    __shared__ float smt[64][65];
    const int b = blockIdx.z;
    const int c0 = blockIdx.y * 64;
    const int n0 = blockIdx.x * 64;
    const int t = threadIdx.x;
    const float* xb = x + (size_t)b * Cn * HWn;

    #pragma unroll
    for (int i = 0; i < 16; i++) {
        int idx = t + i * 256;
        int c = idx >> 6, nn = idx & 63;
        smt[c][nn] = xb[(size_t)(c0 + c) * HWn + n0 + nn];
    }
    __syncthreads();
    __half* ob = Xt + (size_t)b * HWn * Cn;
    #pragma unroll
    for (int i = 0; i < 2; i++) {
        int s = t + i * 256;
        int n = s >> 3, c8 = (s & 7) * 8;
        __half2 h[4];
        #pragma unroll
        for (int j = 0; j < 4; j++)
            h[j] = __floats2half2_rn(smt[c8 + 2 * j][n], smt[c8 + 2 * j + 1][n]);
        *(float4*)&ob[(size_t)(n0 + n) * Cn + c0 + c8] = *(float4*)h;
    }
}

// ---------------------------------------------------------------------------
// round4_h: fp16-round all 4 weight matrices + w0*br bias. 256 blocks.
// ---------------------------------------------------------------------------
__global__ __launch_bounds__(256)
void round4_h(const float* __restrict__ Wk, const float* __restrict__ Wq,
              const float* __restrict__ Wv, const float* __restrict__ Wr,
              const float* __restrict__ br, const float* __restrict__ wdw,
              __half* __restrict__ dst, float* __restrict__ bias)
{
    int i = blockIdx.x * 256 + threadIdx.x;
    dst[i]               = __float2half_rn(Wk[i]);
    dst[i + 1 * Cn * Cn] = __float2half_rn(Wq[i]);
    dst[i + 2 * Cn * Cn] = __float2half_rn(Wv[i]);
    dst[i + 3 * Cn * Cn] = __float2half_rn(Wr[i]);
    if (blockIdx.x == 0) bias[threadIdx.x] = wdw[2 * threadIdx.x] * br[threadIdx.x];
}

// ---------------------------------------------------------------------------
// krow_h: per (b,c) row of K: stats + write softmax(K) fp16.  grid Bn*Cn.
// ---------------------------------------------------------------------------
__global__ __launch_bounds__(256)
void krow_h(const float* __restrict__ K, __half* __restrict__ Kh)
{
    __shared__ float red[256];
    const size_t base = (size_t)blockIdx.x * HWn;
    const int t = threadIdx.x;

    float v[16];
    float m = -INFINITY;
    #pragma unroll
    for (int i = 0; i < 16; i++) {
        v[i] = K[base + t + i * 256];
        m = fmaxf(m, v[i]);
    }
    red[t] = m; __syncthreads();
    for (int s = 128; s > 0; s >>= 1) {
        if (t < s) red[t] = fmaxf(red[t], red[t + s]);
        __syncthreads();
    }
    m = red[0]; __syncthreads();

    float sum = 0.f;
    #pragma unroll
    for (int i = 0; i < 16; i++) sum += expf(v[i] - m);
    red[t] = sum; __syncthreads();
    for (int s = 128; s > 0; s >>= 1) {
        if (t < s) red[t] += red[t + s];
        __syncthreads();
    }
    float inv = 1.0f / red[0];
    #pragma unroll
    for (int i = 0; i < 16; i++)
        Kh[base + t + i * 256] = __float2half_rn(expf(v[i] - m) * inv);
}

// ---------------------------------------------------------------------------
// shuffle block reductions (exact)
// ---------------------------------------------------------------------------
__device__ __forceinline__ float blk_max(float v, float* red, int t)
{
    #pragma unroll
    for (int o = 16; o > 0; o >>= 1)
        v = fmaxf(v, __shfl_xor_sync(0xffffffffu, v, o));
    if ((t & 31) == 0) red[t >> 5] = v;
    __syncthreads();
    if (t < 32) {
        float r = red[t & 7];
        #pragma unroll
        for (int o = 4; o > 0; o >>= 1)
            r = fmaxf(r, __shfl_xor_sync(0xffffffffu, r, o));
        if (t == 0) red[0] = r;
    }
    __syncthreads();
    float out = red[0];
    __syncthreads();
    return out;
}

__device__ __forceinline__ float blk_sum(float v, float* red, int t)
{
    #pragma unroll
    for (int o = 16; o > 0; o >>= 1)
        v += __shfl_xor_sync(0xffffffffu, v, o);
    if ((t & 31) == 0) red[t >> 5] = v;
    __syncthreads();
    if (t < 32) {
        float r = red[t & 7];
        #pragma unroll
        for (int o = 4; o > 0; o >>= 1)
            r += __shfl_xor_sync(0xffffffffu, r, o);
        if (t == 0) red[0] = r;
    }
    __syncthreads();
    float out = red[0];
    __syncthreads();
    return out;
}

// ---------------------------------------------------------------------------
// gauss_pyr: Laplacian pyramid, stats, and DIRECT fp16 operand emission:
//   A1h=softmax(x), B1h=fp16(x); A2h=softmax(x-G1), B2h=fp16(x-G1);
//   A3h=softmax(G1-G2), B3h=fp16(G1-G2).  No G1/G2 global writes.
// grid = Bn*Cn, block 256.
// ---------------------------------------------------------------------------
struct G5 { float w[5]; };

__global__ __launch_bounds__(256)
void gauss_pyr(const float* __restrict__ x, G5 w3, G5 w5,
               __half* __restrict__ A1h, __half* __restrict__ B1h,
               __half* __restrict__ A2h, __half* __restrict__ B2h,
               __half* __restrict__ A3h, __half* __restrict__ B3h)
{
    __shared__ float sa[68][72];
    __shared__ float sb_[68][72];
    __shared__ float red[8];

    const int img = blockIdx.x;
    const int t = threadIdx.x;
    const size_t base = (size_t)img * HWn;
    const float* ip = x + base;

    for (int i = t; i < 68 * 72; i += 256) {
        (&sa[0][0])[i] = 0.f;
        (&sb_[0][0])[i] = 0.f;
    }
    __syncthreads();

    float xv[16];
    #pragma unroll
    for (int i = 0; i < 16; i++) {
        int px = t + i * 256;
        xv[i] = ip[px];
        sa[(px >> 6) + 2][(px & 63) + 2] = xv[i];
    }
    __syncthreads();

    // level 0: softmax(x) + raw x
    {
        float m = -INFINITY;
        #pragma unroll
        for (int i = 0; i < 16; i++) m = fmaxf(m, xv[i]);
        m = blk_max(m, red, t);
        float s = 0.f;
        #pragma unroll
        for (int i = 0; i < 16; i++) s += expf(xv[i] - m);
        s = blk_sum(s, red, t);
        float inv = 1.0f / s;
        #pragma unroll
        for (int i = 0; i < 16; i++) {
            int px = t + i * 256;
            A1h[base + px] = __float2half_rn(expf(xv[i] - m) * inv);
            B1h[base + px] = __float2half_rn(xv[i]);
        }
    }

    // level 1: G1 = gauss3(x) (5-tap, w3 zero-padded)
    #pragma unroll
    for (int i = 0; i < 16; i++) {
        int px = t + i * 256, y = (px >> 6) + 2, c = (px & 63) + 2;
        float a = 0.f;
        #pragma unroll
        for (int d = 0; d < 5; d++) a += w3.w[d] * sa[y][c + d - 2];
        sb_[y][c] = a;
    }
    __syncthreads();

    float g1[16];
    #pragma unroll
    for (int i = 0; i < 16; i++) {
        int px = t + i * 256, y = (px >> 6) + 2, c = (px & 63) + 2;
        float a = 0.f;
        #pragma unroll
        for (int d = 0; d < 5; d++) a += w3.w[d] * sb_[y + d - 2][c];
        g1[i] = a;
    }

    // level-1 Laplacian: x - G1
    {
        float m = -INFINITY;
        #pragma unroll
        for (int i = 0; i < 16; i++) m = fmaxf(m, xv[i] - g1[i]);
        m = blk_max(m, red, t);
        float s = 0.f;
        #pragma unroll
        for (int i = 0; i < 16; i++) s += expf(xv[i] - g1[i] - m);
        s = blk_sum(s, red, t);
        float inv = 1.0f / s;
        #pragma unroll
        for (int i = 0; i < 16; i++) {
            int px = t + i * 256;
            float d = xv[i] - g1[i];
            A2h[base + px] = __float2half_rn(expf(d - m) * inv);
            B2h[base + px] = __float2half_rn(d);
        }
    }

    // load G1 into sa interior (all sa reads finished; barriers above ordered)
    #pragma unroll
    for (int i = 0; i < 16; i++) {
        int px = t + i * 256;
        sa[(px >> 6) + 2][(px & 63) + 2] = g1[i];
    }
    __syncthreads();

    // level 2: G2 = gauss5(G1)
    #pragma unroll
    for (int i = 0; i < 16; i++) {
        int px = t + i * 256, y = (px >> 6) + 2, c = (px & 63) + 2;
        float a = 0.f;
        #pragma unroll
        for (int d = 0; d < 5; d++) a += w5.w[d] * sa[y][c + d - 2];
        sb_[y][c] = a;
    }
    __syncthreads();

    float dv[16];
    #pragma unroll
    for (int i = 0; i < 16; i++) {
        int px = t + i * 256, y = (px >> 6) + 2, c = (px & 63) + 2;
        float a = 0.f;
        #pragma unroll
        for (int d = 0; d < 5; d++) a += w5.w[d] * sb_[y + d - 2][c];
        dv[i] = g1[i] - a;
    }
    {
        float m = -INFINITY;
        #pragma unroll
        for (int i = 0; i < 16; i++) m = fmaxf(m, dv[i]);
        m = blk_max(m, red, t);
        float s = 0.f;
        #pragma unroll
        for (int i = 0; i < 16; i++) s += expf(dv[i] - m);
        s = blk_sum(s, red, t);
        float inv = 1.0f / s;
        #pragma unroll
        for (int i = 0; i < 16; i++) {
            int px = t + i * 256;
            A3h[base + px] = __float2half_rn(expf(dv[i] - m) * inv);
            B3h[base + px] = __float2half_rn(dv[i]);
        }
    }
}

// ---------------------------------------------------------------------------
// softmax over channel axis (256) of Q fp32 [c][n]; writes Qt fp16 [n][c].
// ---------------------------------------------------------------------------
__global__ __launch_bounds__(256)
void softmax_c_qt(const float* __restrict__ Q, __half* __restrict__ Qt)
{
    extern __shared__ float smf[];
    const int P = 65;
    float* red = smf + 256 * P;
    const int blk = blockIdx.x;
    const int b = blk >> 6, n0 = (blk & 63) * 64;
    const float* base = Q + (size_t)b * Cn * HWn + n0;
    const int t = threadIdx.x, nl = t & 63, cs = t >> 6;

    #pragma unroll 4
    for (int i = 0; i < 64; i++) {
        int c = cs * 64 + i;
        smf[c * P + nl] = base[(size_t)c * HWn + nl];
    }
    __syncthreads();
    float m = -INFINITY;
    #pragma unroll 4
    for (int i = 0; i < 64; i++) m = fmaxf(m, smf[(cs * 64 + i) * P + nl]);
    red[cs * 64 + nl] = m;
    __syncthreads();
    if (t < 64)
        red[t] = fmaxf(fmaxf(red[t], red[64 + t]), fmaxf(red[128 + t], red[192 + t]));
    __syncthreads();
    m = red[nl];
    __syncthreads();
    float s = 0.f;
    #pragma unroll 4
    for (int i = 0; i < 64; i++) {
        int c = cs * 64 + i;
        float e = expf(smf[c * P + nl] - m);
        smf[c * P + nl] = e;
        s += e;
    }
    red[cs * 64 + nl] = s;
    __syncthreads();
    if (t < 64) red[t] = red[t] + red[64 + t] + red[128 + t] + red[192 + t];
    __syncthreads();
    float inv = 1.0f / red[nl];
    __half* ob = Qt + (size_t)b * HWn * Cn + (size_t)(n0 + nl) * Cn;
    #pragma unroll
    for (int i = 0; i < 64; i += 8) {
        int c = cs * 64 + i;
        __half2 h[4];
        #pragma unroll
        for (int j = 0; j < 4; j++)
            h[j] = __floats2half2_rn(smf[(c + 2 * j) * P + nl] * inv,
                                     smf[(c + 2 * j + 1) * P + nl] * inv);
        *(float4*)&ob[c] = *(float4*)h;
    }
}

// ---------------------------------------------------------------------------
// ctx reduce -> fp16
// ---------------------------------------------------------------------------
__global__ __launch_bounds__(256)
void reduce_ctx_h(const float* __restrict__ part, __half* __restrict__ ctx)
{
    const int e = blockIdx.x * 256 + threadIdx.x;
    const int b = e >> 16, r = e & 65535;
    float v = 0.f;
    #pragma unroll
    for (int s = 0; s < SPLITK; s++)
        v += part[((size_t)(b * SPLITK + s) << 16) + r];
    ctx[e] = __float2half_rn(v);
}

// ---------------------------------------------------------------------------
// row softmax (256) of split-K gram partials, accumulate into att (fp32)
// ---------------------------------------------------------------------------
__global__ __launch_bounds__(256)
void softmax_rows_accum(const float* __restrict__ part, float* __restrict__ att, int init)
{
    __shared__ float red[256];
    const int row = blockIdx.x;
    const int b = row >> 8, i = row & 255;
    const int t = threadIdx.x;

    float v = 0.f;
    size_t base = ((size_t)b * SPLITK << 16) + (size_t)i * Cn + t;
    #pragma unroll
    for (int s = 0; s < SPLITK; s++) v += part[base + ((size_t)s << 16)];

    red[t] = v; __syncthreads();
    for (int s = 128; s > 0; s >>= 1) {
        if (t < s) red[t] = fmaxf(red[t], red[t + s]);
        __syncthreads();
    }
    float m = red[0]; __syncthreads();
    float e = expf(v - m);
    red[t] = e; __syncthreads();
    for (int s = 128; s > 0; s >>= 1) {
        if (t < s) red[t] += red[t + s];
        __syncthreads();
    }
    float r = e / red[0];
    size_t o = (size_t)row * Cn + t;
    att[o] = init ? r : (att[o] + r);
}

// ---------------------------------------------------------------------------
// Mc[b][m][k] = fp16( w0[m]*Meff[b][m][k] + w1[m]*att[b][k][m] )
// ---------------------------------------------------------------------------
__global__ __launch_bounds__(256)
void combine_mc_h(const float* __restrict__ Meff, const float* __restrict__ att,
                  const float* __restrict__ wdw, __half* __restrict__ Mc)
{
    __shared__ float ts[32][33];
    const int b = blockIdx.z, m0 = blockIdx.y * 32, k0 = blockIdx.x * 32;
    const int tx = threadIdx.x & 31, ty = threadIdx.x >> 5;
    const float* attb = att + (size_t)b * Cn * Cn;

    #pragma unroll
    for (int j = 0; j < 4; j++)
        ts[ty + j * 8][tx] = attb[(size_t)(k0 + ty + j * 8) * Cn + m0 + tx];
    __syncthreads();

    const float* mb = Meff + (size_t)b * Cn * Cn;
    __half* ob = Mc + (size_t)b * Cn * Cn;
    #pragma unroll
    for (int j = 0; j < 4; j++) {
        int m = m0 + ty + j * 8, k = k0 + tx;
        float w0 = wdw[2 * m], w1 = wdw[2 * m + 1];
        ob[(size_t)m * Cn + k] =
            __float2half_rn(w0 * mb[(size_t)m * Cn + k] + w1 * ts[tx][ty + j * 8]);
    }
}

// ---------------------------------------------------------------------------
// host
// ---------------------------------------------------------------------------
static void make_gauss1d(int ksize, double sigma, float* w)
{
    double g[5], s = 0.0;
    for (int i = 0; i < ksize; i++) {
        double d = (double)i - (ksize - 1) / 2.0;
        g[i] = exp(-(d * d) / (2.0 * sigma * sigma));
        s += g[i];
    }
    for (int i = 0; i < ksize; i++) w[i] = (float)(g[i] / s);
}

extern "C" void kernel_launch(void* const* d_in, const int* in_sizes, int n_in,
                              void* d_out, int out_size)
{
    (void)in_sizes; (void)n_in; (void)out_size;
    const float* x   = (const float*)d_in[0];
    const float* Wk  = (const float*)d_in[1];
    const float* bk  = (const float*)d_in[2];
    const float* Wq  = (const float*)d_in[3];
    const float* bq  = (const float*)d_in[4];
    const float* Wv  = (const float*)d_in[5];
    const float* bv  = (const float*)d_in[6];
    const float* Wr  = (const float*)d_in[7];
    const float* br  = (const float*)d_in[8];
    const float* wdw = (const float*)d_in[9];
    float* out = (float*)d_out;

    __half *gXt, *gQt, *gWh, *gCtxh, *gMch, *gKh, *gVh;
    __half *gA1, *gB1, *gA2, *gB2, *gA3, *gB3;
    float *gK, *gQ, *gAttm, *gMeff, *gPart, *gBias;
    cudaGetSymbolAddress((void**)&gXt,   g_Xt);
    cudaGetSymbolAddress((void**)&gQt,   g_Qt);
    cudaGetSymbolAddress((void**)&gWh,   g_Wh);
    cudaGetSymbolAddress((void**)&gCtxh, g_Ctxh);
    cudaGetSymbolAddress((void**)&gMch,  g_Mch);
    cudaGetSymbolAddress((void**)&gKh,   g_Kh);
    cudaGetSymbolAddress((void**)&gVh,   g_Vh);
    cudaGetSymbolAddress((void**)&gA1,   g_A1h);
    cudaGetSymbolAddress((void**)&gB1,   g_B1h);
    cudaGetSymbolAddress((void**)&gA2,   g_A2h);
    cudaGetSymbolAddress((void**)&gB2,   g_B2h);
    cudaGetSymbolAddress((void**)&gA3,   g_A3h);
    cudaGetSymbolAddress((void**)&gB3,   g_B3h);
    cudaGetSymbolAddress((void**)&gK,    g_K);
    cudaGetSymbolAddress((void**)&gQ,    g_Q);
    cudaGetSymbolAddress((void**)&gAttm, g_Attm);
    cudaGetSymbolAddress((void**)&gMeff, g_Meff);
    cudaGetSymbolAddress((void**)&gPart, g_Part);
    cudaGetSymbolAddress((void**)&gBias, g_Bias);

    const int SM_SMC = (256 * 65 + 512) * 4;
    cudaFuncSetAttribute(conv3_h,       cudaFuncAttributeMaxDynamicSharedMemorySize, SM_GEMM3);
    cudaFuncSetAttribute(gemm_h,        cudaFuncAttributeMaxDynamicSharedMemorySize, SM_GEMM3);
    cudaFuncSetAttribute(gram_g,        cudaFuncAttributeMaxDynamicSharedMemorySize, SM_GEMM3);
    cudaFuncSetAttribute(softmax_c_qt,  cudaFuncAttributeMaxDynamicSharedMemorySize, SM_SMC);

    const double SIGMA = 1.6;
    const double S_VAL = cbrt(2.0);
    G5 g3 = {}, g5 = {};
    float t3[5];
    make_gauss1d(3, SIGMA, t3);
    g3.w[0] = 0.f; g3.w[1] = t3[0]; g3.w[2] = t3[1]; g3.w[3] = t3[2]; g3.w[4] = 0.f;
    make_gauss1d(5, SIGMA * S_VAL, g5.w);

    dim3 gConv3(HWn / 128, 6, Bn);                // 1536 blocks
    dim3 gGram(Cn / 128, Cn / 128, Bn * SPLITK);  // (2, 2, 64)
    dim3 gMeffG(Cn / 128, Cn / 128, Bn);          // (2, 2, 8)
    dim3 gFinal(HWn / 128, Cn / 128, Bn);         // (32, 2, 8)
    dim3 gComb(Cn / 32, Cn / 32, Bn);             // (8, 8, 8)
    dim3 gPrep(HWn / 64, Cn / 64, Bn);            // (64, 4, 8)

    // prep
    round4_h<<<Cn * Cn / 256, 256>>>(Wk, Wq, Wv, Wr, br, wdw, gWh, gBias);
    prep_x<<<gPrep, 256>>>(x, gXt);

    // convs (K,Q fp32; V fp16)
    conv3_h<<<gConv3, 256, SM_GEMM3>>>(gWh, gXt, bk, bq, bv, gK, gQ, gVh);

    // fp16 operand materialization
    krow_h<<<Bn * Cn, 256>>>(gK, gKh);
    softmax_c_qt<<<Bn * 64, 256, SM_SMC>>>(gQ, gQt);
    gauss_pyr<<<Bn * Cn, 256>>>(x, g3, g5, gA1, gB1, gA2, gB2, gA3, gB3);

    // efficient attention: ctx = softmax(K) @ V^T  (pure fp16 GEMM)
    gram_g<<<gGram, 256, SM_GEMM3>>>(gKh, gVh, gPart);
    reduce_ctx_h<<<BCC / 256, 256>>>(gPart, gCtxh);

    // Meff = Wr @ ctx^T
    gemm_h<<<gMeffG, 256, SM_GEMM3>>>(gWh + 3 * (size_t)Cn * Cn, 0,
                                      gCtxh, (size_t)Cn * Cn,
                                      nullptr, gMeff, Cn, (size_t)Cn * Cn);

    // channel attention: 3 Laplacian levels (pure fp16 GEMMs, reused slab)
    gram_g<<<gGram, 256, SM_GEMM3>>>(gA1, gB1, gPart);
    softmax_rows_accum<<<Bn * Cn, 256>>>(gPart, gAttm, 1);

    gram_g<<<gGram, 256, SM_GEMM3>>>(gA2, gB2, gPart);
    softmax_rows_accum<<<Bn * Cn, 256>>>(gPart, gAttm, 0);

    gram_g<<<gGram, 256, SM_GEMM3>>>(gA3, gB3, gPart);
    softmax_rows_accum<<<Bn * Cn, 256>>>(gPart, gAttm, 0);

    // fold: out = Mc @ Qt^T + w0*br
    combine_mc_h<<<gComb, 256>>>(gMeff, gAttm, wdw, gMch);
    gemm_h<<<gFinal, 256, SM_GEMM3>>>(gMch, (size_t)Cn * Cn,
                                      gQt, (size_t)HWn * Cn,
                                      gBias, out, HWn, (size_t)Cn * HWn);
}

// round 17
// speedup vs baseline: 1.6105x; 1.0660x over previous
#include <cuda_runtime.h>
#include <cuda_fp16.h>
#include <math.h>
#include <stdint.h>

// ---------------------------------------------------------------------------
// EfficientFrequencyAttention  B=8, C=256, H=W=64
// Round 17 (= round 16 resubmitted after infra failure):
// all 4 grams in ONE launch (SPLITK=4, 33.5MB L2-resident partials),
// merged rows3_accum. Rest as round 15.
// ---------------------------------------------------------------------------
#define Bn  8
#define Cn  256
#define HWn 4096
#define BCHW (Bn*Cn*HWn)   // 8,388,608
#define BCC  (Bn*Cn*Cn)    // 524,288
#define SPK  4             // split-K per gram level

// ----------------------------- scratch (static, no allocation) -------------
__device__ __half g_Xt  [BCHW];          // x transposed fp16: [b][n][c]
__device__ __half g_Qt  [BCHW];          // softmax_c(Q) transposed fp16: [b][n][c]
__device__ __half g_Wh  [4 * Cn * Cn];   // fp16 Wk,Wq,Wv,Wr  [m][k]
__device__ __half g_Ctxh[BCC];           // ctx fp16
__device__ __half g_Mch [BCC];           // combined final A fp16 [m][k]
__device__ float  g_K   [BCHW];          // conv K fp32 [c][n]
__device__ float  g_Q   [BCHW];          // conv Q fp32 [c][n]
__device__ __half g_Kh  [BCHW];          // softmax(K) fp16
__device__ __half g_Vh  [BCHW];          // V fp16
__device__ __half g_A1h [BCHW];          // softmax(x) fp16
__device__ __half g_B1h [BCHW];          // x fp16
__device__ __half g_A2h [BCHW];          // softmax(x-G1) fp16
__device__ __half g_B2h [BCHW];          // (x-G1) fp16
__device__ __half g_A3h [BCHW];          // softmax(G1-G2) fp16
__device__ __half g_B3h [BCHW];          // (G1-G2) fp16
__device__ float  g_Attm[BCC];
__device__ float  g_Meff[BCC];
__device__ float  g_Part[4 * Bn * SPK * Cn * Cn];  // 33.5 MB (L2-resident)
__device__ float  g_Bias[Cn];

// ----------------------------- helpers -------------------------------------
__device__ __forceinline__ void mma16(float* c, const unsigned* a, const unsigned* b) {
    asm volatile(
        "mma.sync.aligned.m16n8k16.row.col.f32.f16.f16.f32 "
        "{%0,%1,%2,%3},{%4,%5,%6,%7},{%8,%9},{%0,%1,%2,%3};\n"
        : "+f"(c[0]), "+f"(c[1]), "+f"(c[2]), "+f"(c[3])
        : "r"(a[0]), "r"(a[1]), "r"(a[2]), "r"(a[3]),
          "r"(b[0]), "r"(b[1]));
}

__device__ __forceinline__ void ldsm4(unsigned& r0, unsigned& r1,
                                      unsigned& r2, unsigned& r3, uint32_t addr) {
    asm volatile("ldmatrix.sync.aligned.m8n8.x4.shared.b16 {%0,%1,%2,%3}, [%4];"
        : "=r"(r0), "=r"(r1), "=r"(r2), "=r"(r3) : "r"(addr));
}

__device__ __forceinline__ void cp16(uint32_t dst, const void* src) {
    asm volatile("cp.async.ca.shared.global [%0], [%1], 16;" :: "r"(dst), "l"(src));
}
#define CP_COMMIT() asm volatile("cp.async.commit_group;")
#define CP_WAIT1()  asm volatile("cp.async.wait_group 1;")
#define CP_WAIT0()  asm volatile("cp.async.wait_group 0;")

// fp16 tile: 128 rows x 32 k-halves, row stride 20 half2 (80 B)
#define HS2   20
#define TILE_U (128 * HS2)
#define TILE_B (TILE_U * 4)       // 10240 bytes
#define STG_B  (2 * TILE_B)       // 20480 bytes
#define SM_GEMM3 (3 * STG_B)      // 61440 bytes

// ---------------------------------------------------------------------------
// LDSM chunk: 12 LDSM.x4 + 32 HMMA per warp-chunk; conflict-free @ 80B stride.
// ---------------------------------------------------------------------------
__device__ __forceinline__ void gemm_chunk_ldsm(uint32_t aTile, uint32_t bTile,
                                                const uint32_t aOff[2],
                                                const uint32_t bOff[4],
                                                float acc[2][8][4])
{
    #pragma unroll
    for (int ks = 0; ks < 2; ks++) {
        const uint32_t ka = ks * 32;
        unsigned af[2][4], bf[8][2];
        #pragma unroll
        for (int mi = 0; mi < 2; mi++)
            ldsm4(af[mi][0], af[mi][1], af[mi][2], af[mi][3],
                  aTile + aOff[mi] + ka);
        #pragma unroll
        for (int p = 0; p < 4; p++)
            ldsm4(bf[2 * p][0], bf[2 * p][1], bf[2 * p + 1][0], bf[2 * p + 1][1],
                  bTile + bOff[p] + ka);
        #pragma unroll
        for (int mi = 0; mi < 2; mi++)
            #pragma unroll
            for (int ni = 0; ni < 8; ni++)
                mma16(acc[mi][ni], af[mi], bf[ni]);
    }
}

// 3-stage pipelined body: wait(c) / in-flight(c+1) / issue(c+2); 1 sync/chunk.
template <typename IssueFn>
__device__ __forceinline__ void gemm_body3(IssueFn issue, uint32_t sb,
                                           const uint32_t aOff[2],
                                           const uint32_t bOff[4],
                                           int NC, float acc[2][8][4])
{
    issue(0, 0);
    issue(1, 1);
    for (int c = 0; c < NC; c++) {
        if (c == NC - 1) { CP_WAIT0(); }
        else             { CP_WAIT1(); }
        __syncthreads();
        if (c + 2 < NC) issue(c + 2, (c + 2) % 3);
        const uint32_t stg = (uint32_t)(c % 3) * STG_B;
        gemm_chunk_ldsm(sb + stg, sb + stg + TILE_B, aOff, bOff, acc);
    }
}

__device__ __forceinline__ void frag_offsets(int lane, int wm, int wn,
                                             uint32_t aOff[2], uint32_t bOff[4])
{
    const int quad = lane >> 3, r8 = lane & 7;
    #pragma unroll
    for (int mi = 0; mi < 2; mi++)
        aOff[mi] = (uint32_t)((wm + mi * 16 + 8 * (quad & 1) + r8) * 80 + (quad >> 1) * 16);
    #pragma unroll
    for (int p = 0; p < 4; p++)
        bOff[p] = (uint32_t)((wn + 16 * p + 8 * (quad >> 1) + r8) * 80 + (quad & 1) * 16);
}

// ---------------------------------------------------------------------------
// conv3_h: all three 1x1 convs in ONE launch. K,Q -> fp32; V -> fp16.
// grid (32, 6, 8)
// ---------------------------------------------------------------------------
__global__ __launch_bounds__(256)
void conv3_h(const __half* __restrict__ Wh, const __half* __restrict__ Xt,
             const float* __restrict__ bk, const float* __restrict__ bq,
             const float* __restrict__ bv,
             float* __restrict__ Ko, float* __restrict__ Qo,
             __half* __restrict__ Vh)
{
    extern __shared__ unsigned sm[];
    uint32_t sb = (uint32_t)__cvta_generic_to_shared(sm);

    const int wsel = blockIdx.y >> 1;
    const int m0 = (blockIdx.y & 1) * 128;
    const int b  = blockIdx.z;
    const int n0 = blockIdx.x * 128;
    const int t  = threadIdx.x;
    const __half* Ab = Wh + (size_t)wsel * Cn * Cn;
    const __half* Bb = Xt + (size_t)b * HWn * Cn;
    const float* bias = wsel == 0 ? bk : (wsel == 1 ? bq : bv);

    const int lane = t & 31, warp = t >> 5;
    const int wm = (warp & 3) * 32, wn = (warp >> 2) * 64;
    uint32_t aOff[2], bOff[4];
    frag_offsets(lane, wm, wn, aOff, bOff);

    float acc[2][8][4] = {};

    auto issue = [&](int c, int stg) {
        const int kc = c * 32;
        const uint32_t base = sb + (uint32_t)stg * STG_B;
        #pragma unroll
        for (int i = 0; i < 2; i++) {
            int s = t + i * 256;
            int row = s >> 2, f4 = s & 3;
            cp16(base + (uint32_t)(row * HS2 + f4 * 4) * 4,
                 Ab + (size_t)(m0 + row) * Cn + kc + f4 * 8);
        }
        #pragma unroll
        for (int i = 0; i < 2; i++) {
            int s = t + i * 256;
            int row = s >> 2, f4 = s & 3;
            cp16(base + TILE_B + (uint32_t)(row * HS2 + f4 * 4) * 4,
                 Bb + (size_t)(n0 + row) * Cn + kc + f4 * 8);
        }
        CP_COMMIT();
    };

    gemm_body3(issue, sb, aOff, bOff, Cn / 32, acc);

    const int g = lane >> 2, t4 = lane & 3;
    #pragma unroll
    for (int mi = 0; mi < 2; mi++) {
        int r0 = m0 + wm + mi * 16 + g, r1 = r0 + 8;
        float bv0 = bias[r0], bv1 = bias[r1];
        #pragma unroll
        for (int ni = 0; ni < 8; ni++) {
            int col = n0 + wn + ni * 8 + 2 * t4;
            float2 v0 = {acc[mi][ni][0] + bv0, acc[mi][ni][1] + bv0};
            float2 v1 = {acc[mi][ni][2] + bv1, acc[mi][ni][3] + bv1};
            if (wsel < 2) {
                float* Y = (wsel == 0 ? Ko : Qo) + (size_t)b * Cn * HWn;
                *(float2*)&Y[(size_t)r0 * HWn + col] = v0;
                *(float2*)&Y[(size_t)r1 * HWn + col] = v1;
            } else {
                __half* Yh = Vh + (size_t)b * Cn * HWn;
                __half2 h0 = __floats2half2_rn(v0.x, v0.y);
                __half2 h1 = __floats2half2_rn(v1.x, v1.y);
                *(__half2*)&Yh[(size_t)r0 * HWn + col] = h0;
                *(__half2*)&Yh[(size_t)r1 * HWn + col] = h1;
            }
        }
    }
}

// ---------------------------------------------------------------------------
// gemm_h (fp16 NT, LDSM, 3-stage, ld = Cn): Meff + final GEMM.
// ---------------------------------------------------------------------------
__global__ __launch_bounds__(256)
void gemm_h(const __half* __restrict__ A, size_t aStride,
            const __half* __restrict__ B, size_t bStride,
            const float* __restrict__ bias,
            float* __restrict__ Y, int ldY, size_t yStride)
{
    extern __shared__ unsigned sm[];
    uint32_t sb = (uint32_t)__cvta_generic_to_shared(sm);

    const int b  = blockIdx.z;
    const int m0 = blockIdx.y * 128;
    const int n0 = blockIdx.x * 128;
    const int t  = threadIdx.x;
    const __half* Ab = A + (size_t)b * aStride;
    const __half* Bb = B + (size_t)b * bStride;

    const int lane = t & 31, warp = t >> 5;
    const int wm = (warp & 3) * 32, wn = (warp >> 2) * 64;
    uint32_t aOff[2], bOff[4];
    frag_offsets(lane, wm, wn, aOff, bOff);

    float acc[2][8][4] = {};

    auto issue = [&](int c, int stg) {
        const int kc = c * 32;
        const uint32_t base = sb + (uint32_t)stg * STG_B;
        #pragma unroll
        for (int i = 0; i < 2; i++) {
            int s = t + i * 256;
            int row = s >> 2, f4 = s & 3;
            cp16(base + (uint32_t)(row * HS2 + f4 * 4) * 4,
                 Ab + (size_t)(m0 + row) * Cn + kc + f4 * 8);
        }
        #pragma unroll
        for (int i = 0; i < 2; i++) {
            int s = t + i * 256;
            int row = s >> 2, f4 = s & 3;
            cp16(base + TILE_B + (uint32_t)(row * HS2 + f4 * 4) * 4,
                 Bb + (size_t)(n0 + row) * Cn + kc + f4 * 8);
        }
        CP_COMMIT();
    };

    gemm_body3(issue, sb, aOff, bOff, Cn / 32, acc);

    const int g = lane >> 2, t4 = lane & 3;
    float* Yb = Y + (size_t)b * yStride;
    #pragma unroll
    for (int mi = 0; mi < 2; mi++) {
        int r0 = m0 + wm + mi * 16 + g, r1 = r0 + 8;
        float bv0 = bias ? bias[r0] : 0.f;
        float bv1 = bias ? bias[r1] : 0.f;
        #pragma unroll
        for (int ni = 0; ni < 8; ni++) {
            int col = n0 + wn + ni * 8 + 2 * t4;
            float2 v0 = {acc[mi][ni][0] + bv0, acc[mi][ni][1] + bv0};
            float2 v1 = {acc[mi][ni][2] + bv1, acc[mi][ni][3] + bv1};
            *(float2*)&Yb[(size_t)r0 * ldY + col] = v0;
            *(float2*)&Yb[(size_t)r1 * ldY + col] = v1;
        }
    }
}

// ---------------------------------------------------------------------------
// gram4_g: ALL FOUR grams in one launch (fp16 NT, split-K=4, ld = HWn).
//   z = level*32 + b*4 + s ;  level 0: Kh@Vh, 1: A1@B1, 2: A2@B2, 3: A3@B3
//   part[z][m][n] = sum_{k in split s} A[b,m,k] * B[b,n,k]
// grid (2, 2, 128) = 512 blocks.
// ---------------------------------------------------------------------------
__global__ __launch_bounds__(256)
void gram4_g(const __half* __restrict__ Kh, const __half* __restrict__ Vh,
             const __half* __restrict__ A1, const __half* __restrict__ B1,
             const __half* __restrict__ A2, const __half* __restrict__ B2,
             const __half* __restrict__ A3, const __half* __restrict__ B3,
             float* __restrict__ part)
{
    extern __shared__ unsigned sm[];
    uint32_t sb = (uint32_t)__cvta_generic_to_shared(sm);

    const int z = blockIdx.z;
    const int level = z >> 5;
    const int zz = z & 31;
    const int b = zz >> 2, s = zz & 3;
    const int m0 = blockIdx.y * 128;
    const int n0 = blockIdx.x * 128;
    const int kb = s * (HWn / SPK);     // 1024 K per split
    const int t = threadIdx.x;

    const __half *Asrc, *Bsrc;
    if (level == 0)      { Asrc = Kh; Bsrc = Vh; }
    else if (level == 1) { Asrc = A1; Bsrc = B1; }
    else if (level == 2) { Asrc = A2; Bsrc = B2; }
    else                 { Asrc = A3; Bsrc = B3; }
    const __half* Ab = Asrc + (size_t)b * Cn * HWn;
    const __half* Bb = Bsrc + (size_t)b * Cn * HWn;

    const int lane = t & 31, warp = t >> 5;
    const int wm = (warp & 3) * 32, wn = (warp >> 2) * 64;
    uint32_t aOff[2], bOff[4];
    frag_offsets(lane, wm, wn, aOff, bOff);

    float acc[2][8][4] = {};

    auto issue = [&](int c, int stg) {
        const int kc = kb + c * 32;
        const uint32_t base = sb + (uint32_t)stg * STG_B;
        #pragma unroll
        for (int i = 0; i < 2; i++) {
            int s2 = t + i * 256;
            int row = s2 >> 2, f4 = s2 & 3;
            cp16(base + (uint32_t)(row * HS2 + f4 * 4) * 4,
                 Ab + (size_t)(m0 + row) * HWn + kc + f4 * 8);
        }
        #pragma unroll
        for (int i = 0; i < 2; i++) {
            int s2 = t + i * 256;
            int row = s2 >> 2, f4 = s2 & 3;
            cp16(base + TILE_B + (uint32_t)(row * HS2 + f4 * 4) * 4,
                 Bb + (size_t)(n0 + row) * HWn + kc + f4 * 8);
        }
        CP_COMMIT();
    };

    gemm_body3(issue, sb, aOff, bOff, (HWn / SPK) / 32, acc);  // 32 chunks

    const int g = lane >> 2, t4 = lane & 3;
    float* P = part + (size_t)z * Cn * Cn;
    #pragma unroll
    for (int mi = 0; mi < 2; mi++) {
        int r0 = m0 + wm + mi * 16 + g, r1 = r0 + 8;
        #pragma unroll
        for (int ni = 0; ni < 8; ni++) {
            int col = n0 + wn + ni * 8 + 2 * t4;
            *(float2*)&P[(size_t)r0 * Cn + col] = make_float2(acc[mi][ni][0], acc[mi][ni][1]);
            *(float2*)&P[(size_t)r1 * Cn + col] = make_float2(acc[mi][ni][2], acc[mi][ni][3]);
        }
    }
}

// ---------------------------------------------------------------------------
// prep_x: x fp32 [b][c][n] -> Xt fp16 [b][n][c].  grid (HW/64, C/64, B)
// ---------------------------------------------------------------------------
__global__ __launch_bounds__(256)
void prep_x(const float* __restrict__ x, __half* __restrict__ Xt)
{
    __shared__ float smt[64][65];
    const int b = blockIdx.z;
    const int c0 = blockIdx.y * 64;
    const int n0 = blockIdx.x * 64;
    const int t = threadIdx.x;
    const float* xb = x + (size_t)b * Cn * HWn;

    #pragma unroll
    for (int i = 0; i < 16; i++) {
        int idx = t + i * 256;
        int c = idx >> 6, nn = idx & 63;
        smt[c][nn] = xb[(size_t)(c0 + c) * HWn + n0 + nn];
    }
    __syncthreads();
    __half* ob = Xt + (size_t)b * HWn * Cn;
    #pragma unroll
    for (int i = 0; i < 2; i++) {
        int s = t + i * 256;
        int n = s >> 3, c8 = (s & 7) * 8;
        __half2 h[4];
        #pragma unroll
        for (int j = 0; j < 4; j++)
            h[j] = __floats2half2_rn(smt[c8 + 2 * j][n], smt[c8 + 2 * j + 1][n]);
        *(float4*)&ob[(size_t)(n0 + n) * Cn + c0 + c8] = *(float4*)h;
    }
}

// ---------------------------------------------------------------------------
// round4_h: fp16-round all 4 weight matrices + w0*br bias. 256 blocks.
// ---------------------------------------------------------------------------
__global__ __launch_bounds__(256)
void round4_h(const float* __restrict__ Wk, const float* __restrict__ Wq,
              const float* __restrict__ Wv, const float* __restrict__ Wr,
              const float* __restrict__ br, const float* __restrict__ wdw,
              __half* __restrict__ dst, float* __restrict__ bias)
{
    int i = blockIdx.x * 256 + threadIdx.x;
    dst[i]               = __float2half_rn(Wk[i]);
    dst[i + 1 * Cn * Cn] = __float2half_rn(Wq[i]);
    dst[i + 2 * Cn * Cn] = __float2half_rn(Wv[i]);
    dst[i + 3 * Cn * Cn] = __float2half_rn(Wr[i]);
    if (blockIdx.x == 0) bias[threadIdx.x] = wdw[2 * threadIdx.x] * br[threadIdx.x];
}

// ---------------------------------------------------------------------------
// krow_h: per (b,c) row of K: stats + write softmax(K) fp16.  grid Bn*Cn.
// ---------------------------------------------------------------------------
__global__ __launch_bounds__(256)
void krow_h(const float* __restrict__ K, __half* __restrict__ Kh)
{
    __shared__ float red[256];
    const size_t base = (size_t)blockIdx.x * HWn;
    const int t = threadIdx.x;

    float v[16];
    float m = -INFINITY;
    #pragma unroll
    for (int i = 0; i < 16; i++) {
        v[i] = K[base + t + i * 256];
        m = fmaxf(m, v[i]);
    }
    red[t] = m; __syncthreads();
    for (int s = 128; s > 0; s >>= 1) {
        if (t < s) red[t] = fmaxf(red[t], red[t + s]);
        __syncthreads();
    }
    m = red[0]; __syncthreads();

    float sum = 0.f;
    #pragma unroll
    for (int i = 0; i < 16; i++) sum += expf(v[i] - m);
    red[t] = sum; __syncthreads();
    for (int s = 128; s > 0; s >>= 1) {
        if (t < s) red[t] += red[t + s];
        __syncthreads();
    }
    float inv = 1.0f / red[0];
    #pragma unroll
    for (int i = 0; i < 16; i++)
        Kh[base + t + i * 256] = __float2half_rn(expf(v[i] - m) * inv);
}

// ---------------------------------------------------------------------------
// shuffle block reductions (exact)
// ---------------------------------------------------------------------------
__device__ __forceinline__ float blk_max(float v, float* red, int t)
{
    #pragma unroll
    for (int o = 16; o > 0; o >>= 1)
        v = fmaxf(v, __shfl_xor_sync(0xffffffffu, v, o));
    if ((t & 31) == 0) red[t >> 5] = v;
    __syncthreads();
    if (t < 32) {
        float r = red[t & 7];
        #pragma unroll
        for (int o = 4; o > 0; o >>= 1)
            r = fmaxf(r, __shfl_xor_sync(0xffffffffu, r, o));
        if (t == 0) red[0] = r;
    }
    __syncthreads();
    float out = red[0];
    __syncthreads();
    return out;
}

__device__ __forceinline__ float blk_sum(float v, float* red, int t)
{
    #pragma unroll
    for (int o = 16; o > 0; o >>= 1)
        v += __shfl_xor_sync(0xffffffffu, v, o);
    if ((t & 31) == 0) red[t >> 5] = v;
    __syncthreads();
    if (t < 32) {
        float r = red[t & 7];
        #pragma unroll
        for (int o = 4; o > 0; o >>= 1)
            r += __shfl_xor_sync(0xffffffffu, r, o);
        if (t == 0) red[0] = r;
    }
    __syncthreads();
    float out = red[0];
    __syncthreads();
    return out;
}

// ---------------------------------------------------------------------------
// gauss_pyr: Laplacian pyramid + stats + direct fp16 operand emission.
// ---------------------------------------------------------------------------
struct G5 { float w[5]; };

__global__ __launch_bounds__(256)
void gauss_pyr(const float* __restrict__ x, G5 w3, G5 w5,
               __half* __restrict__ A1h, __half* __restrict__ B1h,
               __half* __restrict__ A2h, __half* __restrict__ B2h,
               __half* __restrict__ A3h, __half* __restrict__ B3h)
{
    __shared__ float sa[68][72];
    __shared__ float sb_[68][72];
    __shared__ float red[8];

    const int img = blockIdx.x;
    const int t = threadIdx.x;
    const size_t base = (size_t)img * HWn;
    const float* ip = x + base;

    for (int i = t; i < 68 * 72; i += 256) {
        (&sa[0][0])[i] = 0.f;
        (&sb_[0][0])[i] = 0.f;
    }
    __syncthreads();

    float xv[16];
    #pragma unroll
    for (int i = 0; i < 16; i++) {
        int px = t + i * 256;
        xv[i] = ip[px];
        sa[(px >> 6) + 2][(px & 63) + 2] = xv[i];
    }
    __syncthreads();

    {
        float m = -INFINITY;
        #pragma unroll
        for (int i = 0; i < 16; i++) m = fmaxf(m, xv[i]);
        m = blk_max(m, red, t);
        float s = 0.f;
        #pragma unroll
        for (int i = 0; i < 16; i++) s += expf(xv[i] - m);
        s = blk_sum(s, red, t);
        float inv = 1.0f / s;
        #pragma unroll
        for (int i = 0; i < 16; i++) {
            int px = t + i * 256;
            A1h[base + px] = __float2half_rn(expf(xv[i] - m) * inv);
            B1h[base + px] = __float2half_rn(xv[i]);
        }
    }

    #pragma unroll
    for (int i = 0; i < 16; i++) {
        int px = t + i * 256, y = (px >> 6) + 2, c = (px & 63) + 2;
        float a = 0.f;
        #pragma unroll
        for (int d = 0; d < 5; d++) a += w3.w[d] * sa[y][c + d - 2];
        sb_[y][c] = a;
    }
    __syncthreads();

    float g1[16];
    #pragma unroll
    for (int i = 0; i < 16; i++) {
        int px = t + i * 256, y = (px >> 6) + 2, c = (px & 63) + 2;
        float a = 0.f;
        #pragma unroll
        for (int d = 0; d < 5; d++) a += w3.w[d] * sb_[y + d - 2][c];
        g1[i] = a;
    }

    {
        float m = -INFINITY;
        #pragma unroll
        for (int i = 0; i < 16; i++) m = fmaxf(m, xv[i] - g1[i]);
        m = blk_max(m, red, t);
        float s = 0.f;
        #pragma unroll
        for (int i = 0; i < 16; i++) s += expf(xv[i] - g1[i] - m);
        s = blk_sum(s, red, t);
        float inv = 1.0f / s;
        #pragma unroll
        for (int i = 0; i < 16; i++) {
            int px = t + i * 256;
            float d = xv[i] - g1[i];
            A2h[base + px] = __float2half_rn(expf(d - m) * inv);
            B2h[base + px] = __float2half_rn(d);
        }
    }

    #pragma unroll
    for (int i = 0; i < 16; i++) {
        int px = t + i * 256;
        sa[(px >> 6) + 2][(px & 63) + 2] = g1[i];
    }
    __syncthreads();

    #pragma unroll
    for (int i = 0; i < 16; i++) {
        int px = t + i * 256, y = (px >> 6) + 2, c = (px & 63) + 2;
        float a = 0.f;
        #pragma unroll
        for (int d = 0; d < 5; d++) a += w5.w[d] * sa[y][c + d - 2];
        sb_[y][c] = a;
    }
    __syncthreads();

    float dv[16];
    #pragma unroll
    for (int i = 0; i < 16; i++) {
        int px = t + i * 256, y = (px >> 6) + 2, c = (px & 63) + 2;
        float a = 0.f;
        #pragma unroll
        for (int d = 0; d < 5; d++) a += w5.w[d] * sb_[y + d - 2][c];
        dv[i] = g1[i] - a;
    }
    {
        float m = -INFINITY;
        #pragma unroll
        for (int i = 0; i < 16; i++) m = fmaxf(m, dv[i]);
        m = blk_max(m, red, t);
        float s = 0.f;
        #pragma unroll
        for (int i = 0; i < 16; i++) s += expf(dv[i] - m);
        s = blk_sum(s, red, t);
        float inv = 1.0f / s;
        #pragma unroll
        for (int i = 0; i < 16; i++) {
            int px = t + i * 256;
            A3h[base + px] = __float2half_rn(expf(dv[i] - m) * inv);
            B3h[base + px] = __float2half_rn(dv[i]);
        }
    }
}

// ---------------------------------------------------------------------------
// softmax over channel axis (256) of Q fp32 [c][n]; writes Qt fp16 [n][c].
// ---------------------------------------------------------------------------
__global__ __launch_bounds__(256)
void softmax_c_qt(const float* __restrict__ Q, __half* __restrict__ Qt)
{
    extern __shared__ float smf[];
    const int P = 65;
    float* red = smf + 256 * P;
    const int blk = blockIdx.x;
    const int b = blk >> 6, n0 = (blk & 63) * 64;
    const float* base = Q + (size_t)b * Cn * HWn + n0;
    const int t = threadIdx.x, nl = t & 63, cs = t >> 6;

    #pragma unroll 4
    for (int i = 0; i < 64; i++) {
        int c = cs * 64 + i;
        smf[c * P + nl] = base[(size_t)c * HWn + nl];
    }
    __syncthreads();
    float m = -INFINITY;
    #pragma unroll 4
    for (int i = 0; i < 64; i++) m = fmaxf(m, smf[(cs * 64 + i) * P + nl]);
    red[cs * 64 + nl] = m;
    __syncthreads();
    if (t < 64)
        red[t] = fmaxf(fmaxf(red[t], red[64 + t]), fmaxf(red[128 + t], red[192 + t]));
    __syncthreads();
    m = red[nl];
    __syncthreads();
    float s = 0.f;
    #pragma unroll 4
    for (int i = 0; i < 64; i++) {
        int c = cs * 64 + i;
        float e = expf(smf[c * P + nl] - m);
        smf[c * P + nl] = e;
        s += e;
    }
    red[cs * 64 + nl] = s;
    __syncthreads();
    if (t < 64) red[t] = red[t] + red[64 + t] + red[128 + t] + red[192 + t];
    __syncthreads();
    float inv = 1.0f / red[nl];
    __half* ob = Qt + (size_t)b * HWn * Cn + (size_t)(n0 + nl) * Cn;
    #pragma unroll
    for (int i = 0; i < 64; i += 8) {
        int c = cs * 64 + i;
        __half2 h[4];
        #pragma unroll
        for (int j = 0; j < 4; j++)
            h[j] = __floats2half2_rn(smf[(c + 2 * j) * P + nl] * inv,
                                     smf[(c + 2 * j + 1) * P + nl] * inv);
        *(float4*)&ob[c] = *(float4*)h;
    }
}

// ---------------------------------------------------------------------------
// ctx reduce (level-0 partials, 4 splits) -> fp16
// ---------------------------------------------------------------------------
__global__ __launch_bounds__(256)
void reduce_ctx_h(const float* __restrict__ part, __half* __restrict__ ctx)
{
    const int e = blockIdx.x * 256 + threadIdx.x;
    const int b = e >> 16, r = e & 65535;
    float v = 0.f;
    #pragma unroll
    for (int s = 0; s < SPK; s++)
        v += part[((size_t)(b * SPK + s) << 16) + r];
    ctx[e] = __float2half_rn(v);
}

// ---------------------------------------------------------------------------
// rows3_accum: reduce 4 splits + row softmax for levels 1..3; single att write.
// grid = Bn*Cn, block 256.
// ---------------------------------------------------------------------------
__global__ __launch_bounds__(256)
void rows3_accum(const float* __restrict__ part, float* __restrict__ att)
{
    __shared__ float red[256];
    const int row = blockIdx.x;
    const int b = row >> 8, i = row & 255;
    const int t = threadIdx.x;

    float a = 0.f;
    #pragma unroll
    for (int lev = 1; lev < 4; lev++) {
        size_t zbase = (size_t)(lev * 32 + b * SPK);
        size_t base = (zbase << 16) + (size_t)i * Cn + t;
        float v = 0.f;
        #pragma unroll
        for (int s = 0; s < SPK; s++) v += part[base + ((size_t)s << 16)];

        red[t] = v; __syncthreads();
        for (int s = 128; s > 0; s >>= 1) {
            if (t < s) red[t] = fmaxf(red[t], red[t + s]);
            __syncthreads();
        }
        float m = red[0]; __syncthreads();
        float e = expf(v - m);
        red[t] = e; __syncthreads();
        for (int s = 128; s > 0; s >>= 1) {
            if (t < s) red[t] += red[t + s];
            __syncthreads();
        }
        a += e / red[0];
        __syncthreads();
    }
    att[(size_t)row * Cn + t] = a;
}

// ---------------------------------------------------------------------------
// Mc[b][m][k] = fp16( w0[m]*Meff[b][m][k] + w1[m]*att[b][k][m] )
// ---------------------------------------------------------------------------
__global__ __launch_bounds__(256)
void combine_mc_h(const float* __restrict__ Meff, const float* __restrict__ att,
                  const float* __restrict__ wdw, __half* __restrict__ Mc)
{
    __shared__ float ts[32][33];
    const int b = blockIdx.z, m0 = blockIdx.y * 32, k0 = blockIdx.x * 32;
    const int tx = threadIdx.x & 31, ty = threadIdx.x >> 5;
    const float* attb = att + (size_t)b * Cn * Cn;

    #pragma unroll
    for (int j = 0; j < 4; j++)
        ts[ty + j * 8][tx] = attb[(size_t)(k0 + ty + j * 8) * Cn + m0 + tx];
    __syncthreads();

    const float* mb = Meff + (size_t)b * Cn * Cn;
    __half* ob = Mc + (size_t)b * Cn * Cn;
    #pragma unroll
    for (int j = 0; j < 4; j++) {
        int m = m0 + ty + j * 8, k = k0 + tx;
        float w0 = wdw[2 * m], w1 = wdw[2 * m + 1];
        ob[(size_t)m * Cn + k] =
            __float2half_rn(w0 * mb[(size_t)m * Cn + k] + w1 * ts[tx][ty + j * 8]);
    }
}

// ---------------------------------------------------------------------------
// host
// ---------------------------------------------------------------------------
static void make_gauss1d(int ksize, double sigma, float* w)
{
    double g[5], s = 0.0;
    for (int i = 0; i < ksize; i++) {
        double d = (double)i - (ksize - 1) / 2.0;
        g[i] = exp(-(d * d) / (2.0 * sigma * sigma));
        s += g[i];
    }
    for (int i = 0; i < ksize; i++) w[i] = (float)(g[i] / s);
}

extern "C" void kernel_launch(void* const* d_in, const int* in_sizes, int n_in,
                              void* d_out, int out_size)
{
    (void)in_sizes; (void)n_in; (void)out_size;
    const float* x   = (const float*)d_in[0];
    const float* Wk  = (const float*)d_in[1];
    const float* bk  = (const float*)d_in[2];
    const float* Wq  = (const float*)d_in[3];
    const float* bq  = (const float*)d_in[4];
    const float* Wv  = (const float*)d_in[5];
    const float* bv  = (const float*)d_in[6];
    const float* Wr  = (const float*)d_in[7];
    const float* br  = (const float*)d_in[8];
    const float* wdw = (const float*)d_in[9];
    float* out = (float*)d_out;

    __half *gXt, *gQt, *gWh, *gCtxh, *gMch, *gKh, *gVh;
    __half *gA1, *gB1, *gA2, *gB2, *gA3, *gB3;
    float *gK, *gQ, *gAttm, *gMeff, *gPart, *gBias;
    cudaGetSymbolAddress((void**)&gXt,   g_Xt);
    cudaGetSymbolAddress((void**)&gQt,   g_Qt);
    cudaGetSymbolAddress((void**)&gWh,   g_Wh);
    cudaGetSymbolAddress((void**)&gCtxh, g_Ctxh);
    cudaGetSymbolAddress((void**)&gMch,  g_Mch);
    cudaGetSymbolAddress((void**)&gKh,   g_Kh);
    cudaGetSymbolAddress((void**)&gVh,   g_Vh);
    cudaGetSymbolAddress((void**)&gA1,   g_A1h);
    cudaGetSymbolAddress((void**)&gB1,   g_B1h);
    cudaGetSymbolAddress((void**)&gA2,   g_A2h);
    cudaGetSymbolAddress((void**)&gB2,   g_B2h);
    cudaGetSymbolAddress((void**)&gA3,   g_A3h);
    cudaGetSymbolAddress((void**)&gB3,   g_B3h);
    cudaGetSymbolAddress((void**)&gK,    g_K);
    cudaGetSymbolAddress((void**)&gQ,    g_Q);
    cudaGetSymbolAddress((void**)&gAttm, g_Attm);
    cudaGetSymbolAddress((void**)&gMeff, g_Meff);
    cudaGetSymbolAddress((void**)&gPart, g_Part);
    cudaGetSymbolAddress((void**)&gBias, g_Bias);

    const int SM_SMC = (256 * 65 + 512) * 4;
    cudaFuncSetAttribute(conv3_h,       cudaFuncAttributeMaxDynamicSharedMemorySize, SM_GEMM3);
    cudaFuncSetAttribute(gemm_h,        cudaFuncAttributeMaxDynamicSharedMemorySize, SM_GEMM3);
    cudaFuncSetAttribute(gram4_g,       cudaFuncAttributeMaxDynamicSharedMemorySize, SM_GEMM3);
    cudaFuncSetAttribute(softmax_c_qt,  cudaFuncAttributeMaxDynamicSharedMemorySize, SM_SMC);

    const double SIGMA = 1.6;
    const double S_VAL = cbrt(2.0);
    G5 g3 = {}, g5 = {};
    float t3[5];
    make_gauss1d(3, SIGMA, t3);
    g3.w[0] = 0.f; g3.w[1] = t3[0]; g3.w[2] = t3[1]; g3.w[3] = t3[2]; g3.w[4] = 0.f;
    make_gauss1d(5, SIGMA * S_VAL, g5.w);

    dim3 gConv3(HWn / 128, 6, Bn);               // 1536 blocks
    dim3 gGram4(Cn / 128, Cn / 128, 4 * 32);     // (2, 2, 128) = 512 blocks
    dim3 gMeffG(Cn / 128, Cn / 128, Bn);         // (2, 2, 8)
    dim3 gFinal(HWn / 128, Cn / 128, Bn);        // (32, 2, 8)
    dim3 gComb(Cn / 32, Cn / 32, Bn);            // (8, 8, 8)
    dim3 gPrep(HWn / 64, Cn / 64, Bn);           // (64, 4, 8)

    // prep
    round4_h<<<Cn * Cn / 256, 256>>>(Wk, Wq, Wv, Wr, br, wdw, gWh, gBias);
    prep_x<<<gPrep, 256>>>(x, gXt);

    // Gaussian pyramid early (independent of convs; feeds gram4)
    gauss_pyr<<<Bn * Cn, 256>>>(x, g3, g5, gA1, gB1, gA2, gB2, gA3, gB3);

    // convs (K,Q fp32; V fp16)
    conv3_h<<<gConv3, 256, SM_GEMM3>>>(gWh, gXt, bk, bq, bv, gK, gQ, gVh);

    // fp16 operand materialization for attention side
    krow_h<<<Bn * Cn, 256>>>(gK, gKh);
    softmax_c_qt<<<Bn * 64, 256, SM_SMC>>>(gQ, gQt);

    // ALL FOUR grams in one launch (KV context + 3 Laplacian levels)
    gram4_g<<<gGram4, 256, SM_GEMM3>>>(gKh, gVh, gA1, gB1, gA2, gB2, gA3, gB3, gPart);

    // epilogues
    reduce_ctx_h<<<BCC / 256, 256>>>(gPart, gCtxh);
    gemm_h<<<gMeffG, 256, SM_GEMM3>>>(gWh + 3 * (size_t)Cn * Cn, 0,
                                      gCtxh, (size_t)Cn * Cn,
                                      nullptr, gMeff, Cn, (size_t)Cn * Cn);
    rows3_accum<<<Bn * Cn, 256>>>(gPart, gAttm);
    combine_mc_h<<<gComb, 256>>>(gMeff, gAttm, wdw, gMch);

    // final: out = Mc @ Qt^T + w0*br
    gemm_h<<<gFinal, 256, SM_GEMM3>>>(gMch, (size_t)Cn * Cn,
                                      gQt, (size_t)HWn * Cn,
                                      gBias, out, HWn, (size_t)Cn * HWn);
}